// round 8
// baseline (speedup 1.0000x reference)
#include <cuda_runtime.h>
#include <cuda_fp16.h>
#include <cstdint>

#define TOTAL   9216
#define DIM     2048
#define HEADS   16
#define HD      128
#define FDIM    8192
#define QKV3    6144

// ---------------- scratch (device globals: allocation-free) ----------------
__device__ __half g_ln  [(size_t)TOTAL * DIM];
__device__ float  g_qkv [(size_t)TOTAL * QKV3];
__device__ __half g_attn[(size_t)TOTAL * DIM];
__device__ float  g_h2  [(size_t)TOTAL * DIM];
__device__ __half g_gate[(size_t)TOTAL * FDIM];
__device__ __half g_up  [(size_t)TOTAL * FDIM];
// fp16 weight copies
__device__ __half g_wqkv [(size_t)QKV3 * DIM];
__device__ __half g_wout [(size_t)DIM * DIM];
__device__ __half g_wgate[(size_t)FDIM * DIM];
__device__ __half g_wup  [(size_t)FDIM * DIM];
__device__ __half g_wdown[(size_t)DIM * FDIM];

__device__ const int c_seqlen[8] = {512, 1024, 2048, 768, 1536, 896, 1280, 1152};

// ---------------- helpers ----------------
__device__ __forceinline__ uint32_t f2tf32(float x) {
    uint32_t r;
    asm("cvt.rna.tf32.f32 %0, %1;" : "=r"(r) : "f"(x));
    return r;
}

__device__ __forceinline__ void mma_tf32(float* c, const uint32_t* a, const uint32_t* b) {
    asm("mma.sync.aligned.m16n8k8.row.col.f32.tf32.tf32.f32 "
        "{%0,%1,%2,%3},{%4,%5,%6,%7},{%8,%9},{%0,%1,%2,%3};"
        : "+f"(c[0]), "+f"(c[1]), "+f"(c[2]), "+f"(c[3])
        : "r"(a[0]), "r"(a[1]), "r"(a[2]), "r"(a[3]), "r"(b[0]), "r"(b[1]));
}

__device__ __forceinline__ void mma_f16(float* c, const uint32_t* a, const uint32_t* b) {
    asm("mma.sync.aligned.m16n8k16.row.col.f32.f16.f16.f32 "
        "{%0,%1,%2,%3},{%4,%5,%6,%7},{%8,%9},{%0,%1,%2,%3};"
        : "+f"(c[0]), "+f"(c[1]), "+f"(c[2]), "+f"(c[3])
        : "r"(a[0]), "r"(a[1]), "r"(a[2]), "r"(a[3]), "r"(b[0]), "r"(b[1]));
}

__device__ __forceinline__ void ldsm_x4(uint32_t* r, uint32_t addr) {
    asm volatile("ldmatrix.sync.aligned.m8n8.x4.shared.b16 {%0,%1,%2,%3}, [%4];"
        : "=r"(r[0]), "=r"(r[1]), "=r"(r[2]), "=r"(r[3]) : "r"(addr));
}

__device__ __forceinline__ void cp_async16(void* smem_dst, const void* gmem_src) {
    uint32_t s = (uint32_t)__cvta_generic_to_shared(smem_dst);
    asm volatile("cp.async.cg.shared.global [%0], [%1], 16;" :: "r"(s), "l"(gmem_src));
}
__device__ __forceinline__ void cp_commit() {
    asm volatile("cp.async.commit_group;");
}

// ================= fp16 GEMM =================
// C[M,N] = A[M,K] * B[N,K]^T (+bias)(+resid), A,B fp16, accum fp32.
// 128x256 tile, 512 threads (16 warps as 2x8, warp tile 64x32), K-chunk 64,
// 4-stage cp.async pipeline, ONE __syncthreads per chunk.
// Stride 72 halves (144B rows): conflict-free LDSM.
#define HSTRIDE 72
#define A_HALFS (128 * HSTRIDE)
#define STAGE_HALFS ((128 + 256) * HSTRIDE)
#define GEMM_SMEM_BYTES (4 * STAGE_HALFS * 2)   // 221184

__device__ __forceinline__ void h_load_stage(const __half* __restrict__ Ab,
                                             const __half* __restrict__ Bb,
                                             int K, __half* As, __half* Bs, int tid)
{
    #pragma unroll
    for (int j = 0; j < 2; j++) {                 // A: 128 rows x 8 groups
        int id = tid + j * 512;
        int r = id >> 3, g = (id & 7) << 3;
        cp_async16(As + r * HSTRIDE + g, Ab + (size_t)r * K + g);
    }
    #pragma unroll
    for (int j = 0; j < 4; j++) {                 // B: 256 rows x 8 groups
        int id = tid + j * 512;
        int r = id >> 3, g = (id & 7) << 3;
        cp_async16(Bs + r * HSTRIDE + g, Bb + (size_t)r * K + g);
    }
}

__global__ __launch_bounds__(512, 1) void gemm_f16_kernel(
    const __half* __restrict__ A, const __half* __restrict__ B,
    const float* __restrict__ bias, const float* __restrict__ resid,
    float* __restrict__ Cf, __half* __restrict__ Ch, int M, int N, int K)
{
    extern __shared__ __half hsm[];
    const uint32_t smemBase = (uint32_t)__cvta_generic_to_shared(hsm);

    const int tid  = threadIdx.x;
    const int lane = tid & 31, warp = tid >> 5;
    const int lq = lane >> 2, lr = lane & 3;
    const int wm = (warp >> 3) * 64, wn = (warp & 7) * 32;
    const int bm = blockIdx.y * 128, bn = blockIdx.x * 256;

    // ldmatrix lane mapping: tr = row-in-8, th = matrix row-half, tq = k-half
    const int tr = lane & 7, th = (lane >> 3) & 1, tq = lane >> 4;
    const uint32_t aoff = (uint32_t)(((wm + tr + th * 8) * HSTRIDE + tq * 8) * 2);
    const uint32_t boff = (uint32_t)(((wn + tr + th * 8) * HSTRIDE + tq * 8) * 2);

    float acc[4][4][4];
    #pragma unroll
    for (int mf = 0; mf < 4; mf++)
        #pragma unroll
        for (int nf = 0; nf < 4; nf++)
            #pragma unroll
            for (int e = 0; e < 4; e++) acc[mf][nf][e] = 0.f;

    const __half* Abase = A + (size_t)bm * K;
    const __half* Bbase = B + (size_t)bn * K;
    const int nk = K >> 6;

    // prologue: stages 0,1,2
    #pragma unroll
    for (int s = 0; s < 3; s++) {
        __half* As = hsm + s * STAGE_HALFS;
        __half* Bs = As + A_HALFS;
        h_load_stage(Abase + s * 64, Bbase + s * 64, K, As, Bs, tid);
        cp_commit();
    }

    for (int i = 0; i < nk; i++) {
        asm volatile("cp.async.wait_group 2;");
        __syncthreads();

        const int st = i & 3;
        const uint32_t stOff = smemBase + (uint32_t)(st * STAGE_HALFS * 2);
        const uint32_t aBase = stOff + aoff;
        const uint32_t bBase = stOff + (uint32_t)(A_HALFS * 2) + boff;

        #pragma unroll
        for (int ks = 0; ks < 4; ks++) {
            const uint32_t kOff = (uint32_t)(ks * 32);   // 16 halves
            uint32_t af[4][4];
            #pragma unroll
            for (int mf = 0; mf < 4; mf++)
                ldsm_x4(af[mf], aBase + (uint32_t)(mf * 16 * HSTRIDE * 2) + kOff);
            uint32_t b0[4], b1[4];
            ldsm_x4(b0, bBase + kOff);
            ldsm_x4(b1, bBase + (uint32_t)(16 * HSTRIDE * 2) + kOff);
            uint32_t bf[4][2] = {{b0[0], b0[2]}, {b0[1], b0[3]},
                                 {b1[0], b1[2]}, {b1[1], b1[3]}};
            #pragma unroll
            for (int mf = 0; mf < 4; mf++)
                #pragma unroll
                for (int nf = 0; nf < 4; nf++)
                    mma_f16(acc[mf][nf], af[mf], bf[nf]);
        }

        // write stage (i+3)&3 — never read under the current barrier window
        if (i + 3 < nk) {
            const int sd = (i + 3) & 3;
            __half* Ad = hsm + sd * STAGE_HALFS;
            __half* Bd = Ad + A_HALFS;
            h_load_stage(Abase + (i + 3) * 64, Bbase + (i + 3) * 64, K, Ad, Bd, tid);
        }
        cp_commit();
    }

    // epilogue
    #pragma unroll
    for (int mf = 0; mf < 4; mf++) {
        #pragma unroll
        for (int nf = 0; nf < 4; nf++) {
            int r0 = bm + wm + mf * 16 + lq;
            int c0 = bn + wn + nf * 8 + lr * 2;
            float b0 = 0.f, b1 = 0.f;
            if (bias) { b0 = bias[c0]; b1 = bias[c0 + 1]; }
            float2 v0 = make_float2(acc[mf][nf][0] + b0, acc[mf][nf][1] + b1);
            float2 v1 = make_float2(acc[mf][nf][2] + b0, acc[mf][nf][3] + b1);
            if (resid) {
                float2 ra = *reinterpret_cast<const float2*>(resid + (size_t)r0 * N + c0);
                float2 rb = *reinterpret_cast<const float2*>(resid + (size_t)(r0 + 8) * N + c0);
                v0.x += ra.x; v0.y += ra.y;
                v1.x += rb.x; v1.y += rb.y;
            }
            if (Ch) {
                *reinterpret_cast<__half2*>(Ch + (size_t)r0 * N + c0) =
                    __floats2half2_rn(v0.x, v0.y);
                *reinterpret_cast<__half2*>(Ch + (size_t)(r0 + 8) * N + c0) =
                    __floats2half2_rn(v1.x, v1.y);
            } else {
                *reinterpret_cast<float2*>(Cf + (size_t)r0 * N + c0) = v0;
                *reinterpret_cast<float2*>(Cf + (size_t)(r0 + 8) * N + c0) = v1;
            }
        }
    }
}

// ---------------- weight convert: fp32 -> fp16 ----------------
__global__ __launch_bounds__(256) void cvtw_kernel(const float4* __restrict__ in,
                                                   __half2* __restrict__ out, int n4)
{
    int i = blockIdx.x * blockDim.x + threadIdx.x;
    if (i < n4) {
        float4 v = in[i];
        out[2 * i]     = __floats2half2_rn(v.x, v.y);
        out[2 * i + 1] = __floats2half2_rn(v.z, v.w);
    }
}

// ---------------- RMSNorm (fp32 in, fp16 out) ----------------
__global__ __launch_bounds__(256) void rmsnorm_kernel(const float* __restrict__ x,
                                                      const float* __restrict__ w,
                                                      __half* __restrict__ y)
{
    int row = blockIdx.x;
    const float4* xr = reinterpret_cast<const float4*>(x + (size_t)row * DIM);
    __half2*      yr = reinterpret_cast<__half2*>(y + (size_t)row * DIM);
    const float4* wr = reinterpret_cast<const float4*>(w);
    int tid = threadIdx.x;

    float4 v0 = xr[tid];
    float4 v1 = xr[tid + 256];
    float ss = v0.x*v0.x + v0.y*v0.y + v0.z*v0.z + v0.w*v0.w
             + v1.x*v1.x + v1.y*v1.y + v1.z*v1.z + v1.w*v1.w;
    #pragma unroll
    for (int o = 16; o; o >>= 1) ss += __shfl_xor_sync(0xffffffffu, ss, o);

    __shared__ float red[8];
    __shared__ float stot;
    if ((tid & 31) == 0) red[tid >> 5] = ss;
    __syncthreads();
    if (tid == 0) {
        float t = 0.f;
        #pragma unroll
        for (int i = 0; i < 8; i++) t += red[i];
        stot = rsqrtf(t * (1.0f / (float)DIM) + 1e-6f);
    }
    __syncthreads();
    float r = stot;

    float4 w0 = wr[tid], w1 = wr[tid + 256];
    yr[2 * tid]             = __floats2half2_rn(v0.x*r*w0.x, v0.y*r*w0.y);
    yr[2 * tid + 1]         = __floats2half2_rn(v0.z*r*w0.z, v0.w*r*w0.w);
    yr[2 * (tid + 256)]     = __floats2half2_rn(v1.x*r*w1.x, v1.y*r*w1.y);
    yr[2 * (tid + 256) + 1] = __floats2half2_rn(v1.z*r*w1.z, v1.w*r*w1.w);
}

// ---------------- Flash attention (tf32 mma; qkv fp32 in, fp16 out) ----------------
#define Q_STRIDE 132
#define K_STRIDE 132
#define V_STRIDE 136
#define LOG2E 1.4426950408889634f

#define ATTN_SMEM_BYTES ((128*Q_STRIDE + 2*64*K_STRIDE + 2*64*V_STRIDE) * 4)

__global__ __launch_bounds__(256) void attn_kernel(const float* __restrict__ qkv,
                                                   __half* __restrict__ out)
{
    extern __shared__ char asm_base[];
    uint32_t* Qs   = reinterpret_cast<uint32_t*>(asm_base);
    float*    Kraw = reinterpret_cast<float*>(asm_base) + 128 * Q_STRIDE;
    float*    Vraw = Kraw + 2 * 64 * K_STRIDE;

    const int tile = blockIdx.x;
    const int h    = blockIdx.y;

    int seq_start = 0, q0 = 0;
    {
        int acc = 0, start = 0;
        #pragma unroll
        for (int s = 0; s < 8; s++) {
            int nt = c_seqlen[s] >> 7;
            if (tile >= acc && tile < acc + nt) {
                seq_start = start; q0 = (tile - acc) << 7;
            }
            acc += nt; start += c_seqlen[s];
        }
    }

    const int tid = threadIdx.x, lane = tid & 31, warp = tid >> 5;
    const int lq = lane >> 2, lr = lane & 3;
    const int nkv = (q0 >> 6) + 2;

    const size_t kv_row0 = (size_t)seq_start * QKV3 + DIM + (size_t)h * HD;

    #pragma unroll
    for (int t = 0; t < 2; t++) {
        float* Kd = Kraw + (t & 1) * (64 * K_STRIDE);
        float* Vd = Vraw + (t & 1) * (64 * V_STRIDE);
        const float* kb = qkv + kv_row0 + (size_t)(t * 64) * QKV3;
        #pragma unroll
        for (int j = 0; j < 8; j++) {
            int i = tid + j * 256;
            int r = i >> 5, dg = (i & 31) << 2;
            cp_async16(Kd + r * K_STRIDE + dg, kb + (size_t)r * QKV3 + dg);
            cp_async16(Vd + r * V_STRIDE + dg, kb + (size_t)r * QKV3 + DIM + dg);
        }
        cp_commit();
    }

    {
        const size_t qbase = (size_t)(seq_start + q0) * QKV3 + (size_t)h * HD;
        #pragma unroll
        for (int j = 0; j < 16; j++) {
            int i = tid + j * 256;
            int r = i >> 5, dg = (i & 31) << 2;
            float4 v = *reinterpret_cast<const float4*>(qkv + qbase + (size_t)r * QKV3 + dg);
            uint4 p;
            p.x = f2tf32(v.x); p.y = f2tf32(v.y); p.z = f2tf32(v.z); p.w = f2tf32(v.w);
            *reinterpret_cast<uint4*>(&Qs[r * Q_STRIDE + dg]) = p;
        }
    }

    float oacc[16][4];
    #pragma unroll
    for (int nf = 0; nf < 16; nf++)
        #pragma unroll
        for (int e = 0; e < 4; e++) oacc[nf][e] = 0.f;
    float m0 = -1e30f, m1 = -1e30f, l0 = 0.f, l1 = 0.f;
    const float scale = 0.08838834764831845f;

    const int qbase_warp = q0 + warp * 16;
    const int srcA = (lane & ~3) | (lr >> 1);
    const int srcB = srcA + 2;

    for (int t = 0; t < nkv; t++) {
        asm volatile("cp.async.wait_group 1;");
        __syncthreads();

        const int j0 = t << 6;
        const float* Kb = Kraw + (t & 1) * (64 * K_STRIDE);
        const float* Vb = Vraw + (t & 1) * (64 * V_STRIDE);
        const bool skipw = (j0 > qbase_warp + 15);

        if (!skipw) {
            float sacc[8][4];
            #pragma unroll
            for (int nf = 0; nf < 8; nf++)
                #pragma unroll
                for (int e = 0; e < 4; e++) sacc[nf][e] = 0.f;

            #pragma unroll
            for (int ks = 0; ks < 16; ks++) {
                int kk = ks * 8;
                uint32_t af[4];
                int mrow = warp * 16 + lq;
                af[0] = Qs[mrow * Q_STRIDE + kk + lr];
                af[1] = Qs[(mrow + 8) * Q_STRIDE + kk + lr];
                af[2] = Qs[mrow * Q_STRIDE + kk + lr + 4];
                af[3] = Qs[(mrow + 8) * Q_STRIDE + kk + lr + 4];
                #pragma unroll
                for (int nf = 0; nf < 8; nf++) {
                    uint32_t bf[2];
                    int ncol = nf * 8 + lq;
                    bf[0] = f2tf32(Kb[ncol * K_STRIDE + kk + lr]);
                    bf[1] = f2tf32(Kb[ncol * K_STRIDE + kk + lr + 4]);
                    mma_tf32(sacc[nf], af, bf);
                }
            }

            const bool diag = (j0 + 63 > qbase_warp);
            const int qr0 = qbase_warp + lq;
            const int qr1 = qr0 + 8;
            float mx0 = -1e30f, mx1 = -1e30f;
            #pragma unroll
            for (int nf = 0; nf < 8; nf++) {
                #pragma unroll
                for (int e = 0; e < 4; e++) {
                    float s = sacc[nf][e] * scale;
                    if (diag) {
                        int kc = j0 + nf * 8 + lr * 2 + (e & 1);
                        int qr = (e < 2) ? qr0 : qr1;
                        if (kc > qr) s = -1e30f;
                    }
                    sacc[nf][e] = s;
                }
                mx0 = fmaxf(mx0, fmaxf(sacc[nf][0], sacc[nf][1]));
                mx1 = fmaxf(mx1, fmaxf(sacc[nf][2], sacc[nf][3]));
            }
            mx0 = fmaxf(mx0, __shfl_xor_sync(0xffffffffu, mx0, 1));
            mx0 = fmaxf(mx0, __shfl_xor_sync(0xffffffffu, mx0, 2));
            mx1 = fmaxf(mx1, __shfl_xor_sync(0xffffffffu, mx1, 1));
            mx1 = fmaxf(mx1, __shfl_xor_sync(0xffffffffu, mx1, 2));

            float mn0 = fmaxf(m0, mx0), mn1 = fmaxf(m1, mx1);
            float c0 = exp2f((m0 - mn0) * LOG2E), c1 = exp2f((m1 - mn1) * LOG2E);
            float s0 = 0.f, s1 = 0.f;
            uint32_t pk[8][4];
            #pragma unroll
            for (int nf = 0; nf < 8; nf++) {
                float p0 = exp2f((sacc[nf][0] - mn0) * LOG2E);
                float p1 = exp2f((sacc[nf][1] - mn0) * LOG2E);
                float p2 = exp2f((sacc[nf][2] - mn1) * LOG2E);
                float p3 = exp2f((sacc[nf][3] - mn1) * LOG2E);
                s0 += p0 + p1; s1 += p2 + p3;
                pk[nf][0] = f2tf32(p0);
                pk[nf][1] = f2tf32(p1);
                pk[nf][2] = f2tf32(p2);
                pk[nf][3] = f2tf32(p3);
            }
            s0 += __shfl_xor_sync(0xffffffffu, s0, 1);
            s0 += __shfl_xor_sync(0xffffffffu, s0, 2);
            s1 += __shfl_xor_sync(0xffffffffu, s1, 1);
            s1 += __shfl_xor_sync(0xffffffffu, s1, 2);
            l0 = l0 * c0 + s0;
            l1 = l1 * c1 + s1;
            m0 = mn0; m1 = mn1;
            #pragma unroll
            for (int nf = 0; nf < 16; nf++) {
                oacc[nf][0] *= c0; oacc[nf][1] *= c0;
                oacc[nf][2] *= c1; oacc[nf][3] *= c1;
            }

            #pragma unroll
            for (int ks = 0; ks < 8; ks++) {
                uint32_t af[4];
                {
                    uint32_t u0 = __shfl_sync(0xffffffffu, pk[ks][0], srcA);
                    uint32_t u1 = __shfl_sync(0xffffffffu, pk[ks][1], srcA);
                    uint32_t u2 = __shfl_sync(0xffffffffu, pk[ks][2], srcA);
                    uint32_t u3 = __shfl_sync(0xffffffffu, pk[ks][3], srcA);
                    uint32_t v0 = __shfl_sync(0xffffffffu, pk[ks][0], srcB);
                    uint32_t v1 = __shfl_sync(0xffffffffu, pk[ks][1], srcB);
                    uint32_t v2 = __shfl_sync(0xffffffffu, pk[ks][2], srcB);
                    uint32_t v3 = __shfl_sync(0xffffffffu, pk[ks][3], srcB);
                    af[0] = (lr & 1) ? u1 : u0;
                    af[1] = (lr & 1) ? u3 : u2;
                    af[2] = (lr & 1) ? v1 : v0;
                    af[3] = (lr & 1) ? v3 : v2;
                }
                int kk = ks * 8;
                #pragma unroll
                for (int nf = 0; nf < 16; nf++) {
                    uint32_t bf[2];
                    int ncol = nf * 8 + lq;
                    bf[0] = f2tf32(Vb[(kk + lr) * V_STRIDE + ncol]);
                    bf[1] = f2tf32(Vb[(kk + lr + 4) * V_STRIDE + ncol]);
                    mma_tf32(oacc[nf], af, bf);
                }
            }
        }

        __syncthreads();

        if (t + 2 < nkv) {
            float* Kd = Kraw + (t & 1) * (64 * K_STRIDE);
            float* Vd = Vraw + (t & 1) * (64 * V_STRIDE);
            const float* kb = qkv + kv_row0 + (size_t)((t + 2) * 64) * QKV3;
            #pragma unroll
            for (int j = 0; j < 8; j++) {
                int i = tid + j * 256;
                int r = i >> 5, dg = (i & 31) << 2;
                cp_async16(Kd + r * K_STRIDE + dg, kb + (size_t)r * QKV3 + dg);
                cp_async16(Vd + r * V_STRIDE + dg, kb + (size_t)r * QKV3 + DIM + dg);
            }
        }
        cp_commit();
    }

    // epilogue -> fp16 (feeds out_proj fp16 GEMM)
    float inv0 = 1.f / l0, inv1 = 1.f / l1;
    int t0 = seq_start + q0 + warp * 16 + lq;
    __half* ob = out + (size_t)t0 * DIM + (size_t)h * HD;
    #pragma unroll
    for (int nf = 0; nf < 16; nf++) {
        int c = nf * 8 + lr * 2;
        *reinterpret_cast<__half2*>(ob + c) =
            __floats2half2_rn(oacc[nf][0] * inv0, oacc[nf][1] * inv0);
        *reinterpret_cast<__half2*>(ob + (size_t)8 * DIM + c) =
            __floats2half2_rn(oacc[nf][2] * inv1, oacc[nf][3] * inv1);
    }
}

// ---------------- sigmoid gate: g = fp16(sigmoid(g) * u) ----------------
__global__ __launch_bounds__(256) void gate_kernel(__half2* __restrict__ g,
                                                   const __half2* __restrict__ u, int n2)
{
    int i = blockIdx.x * blockDim.x + threadIdx.x;
    if (i < n2) {
        float2 gv = __half22float2(g[i]);
        float2 uv = __half22float2(u[i]);
        gv.x = uv.x / (1.f + __expf(-gv.x));
        gv.y = uv.y / (1.f + __expf(-gv.y));
        g[i] = __floats2half2_rn(gv.x, gv.y);
    }
}

// ---------------- launch ----------------
extern "C" void kernel_launch(void* const* d_in, const int* in_sizes, int n_in,
                              void* d_out, int out_size)
{
    const float* hidden     = (const float*)d_in[0];
    const float* ln1_w      = (const float*)d_in[1];
    const float* ln2_w      = (const float*)d_in[2];
    const float* in_proj_w  = (const float*)d_in[3];
    const float* in_proj_b  = (const float*)d_in[4];
    const float* out_proj_w = (const float*)d_in[5];
    const float* out_proj_b = (const float*)d_in[6];
    const float* gate_w     = (const float*)d_in[7];
    const float* up_w       = (const float*)d_in[8];
    const float* down_w     = (const float*)d_in[9];
    float* out = (float*)d_out;

    __half *p_ln, *p_attn, *p_gate, *p_up;
    float  *p_qkv, *p_h2;
    __half *p_wqkv, *p_wout, *p_wgate, *p_wup, *p_wdown;
    cudaGetSymbolAddress((void**)&p_ln,    g_ln);
    cudaGetSymbolAddress((void**)&p_qkv,   g_qkv);
    cudaGetSymbolAddress((void**)&p_attn,  g_attn);
    cudaGetSymbolAddress((void**)&p_h2,    g_h2);
    cudaGetSymbolAddress((void**)&p_gate,  g_gate);
    cudaGetSymbolAddress((void**)&p_up,    g_up);
    cudaGetSymbolAddress((void**)&p_wqkv,  g_wqkv);
    cudaGetSymbolAddress((void**)&p_wout,  g_wout);
    cudaGetSymbolAddress((void**)&p_wgate, g_wgate);
    cudaGetSymbolAddress((void**)&p_wup,   g_wup);
    cudaGetSymbolAddress((void**)&p_wdown, g_wdown);

    cudaFuncSetAttribute((const void*)gemm_f16_kernel,
                         cudaFuncAttributeMaxDynamicSharedMemorySize, GEMM_SMEM_BYTES);
    cudaFuncSetAttribute((const void*)attn_kernel,
                         cudaFuncAttributeMaxDynamicSharedMemorySize, ATTN_SMEM_BYTES);

    // 0. weight fp16 conversion (launch order arranged so ncu -s 5 captures qkv GEMM)
    {
        int n4;
        n4 = (QKV3 * DIM) / 4;   // launch 0
        cvtw_kernel<<<(n4 + 255) / 256, 256>>>((const float4*)in_proj_w, (__half2*)p_wqkv, n4);
        n4 = (DIM * DIM) / 4;    // launch 1
        cvtw_kernel<<<(n4 + 255) / 256, 256>>>((const float4*)out_proj_w, (__half2*)p_wout, n4);
        n4 = (FDIM * DIM) / 4;   // launches 2,3
        cvtw_kernel<<<(n4 + 255) / 256, 256>>>((const float4*)gate_w, (__half2*)p_wgate, n4);
        cvtw_kernel<<<(n4 + 255) / 256, 256>>>((const float4*)up_w, (__half2*)p_wup, n4);
    }

    // launch 4: rmsnorm1 (fp16 out)
    rmsnorm_kernel<<<TOTAL, 256>>>(hidden, ln1_w, p_ln);
    // launch 5: qkv projection (fp32 out for attention) — ncu capture target
    gemm_f16_kernel<<<dim3(QKV3 / 256, TOTAL / 128), 512, GEMM_SMEM_BYTES>>>(
        p_ln, p_wqkv, in_proj_b, nullptr, p_qkv, nullptr, TOTAL, QKV3, DIM);
    // launch 6: down-proj weight conversion (before down GEMM, after capture slot)
    {
        int n4 = (FDIM * DIM) / 4;
        cvtw_kernel<<<(n4 + 255) / 256, 256>>>((const float4*)down_w, (__half2*)p_wdown, n4);
    }
    // attention (fp16 out)
    attn_kernel<<<dim3(TOTAL / 128, HEADS), 256, ATTN_SMEM_BYTES>>>(p_qkv, p_attn);
    // out projection + residual (fp32 out)
    gemm_f16_kernel<<<dim3(DIM / 256, TOTAL / 128), 512, GEMM_SMEM_BYTES>>>(
        p_attn, p_wout, out_proj_b, hidden, p_h2, nullptr, TOTAL, DIM, DIM);
    // rmsnorm2 (fp16 out)
    rmsnorm_kernel<<<TOTAL, 256>>>(p_h2, ln2_w, p_ln);
    // gate & up projections (fp16 out)
    gemm_f16_kernel<<<dim3(FDIM / 256, TOTAL / 128), 512, GEMM_SMEM_BYTES>>>(
        p_ln, p_wgate, nullptr, nullptr, nullptr, p_gate, TOTAL, FDIM, DIM);
    gemm_f16_kernel<<<dim3(FDIM / 256, TOTAL / 128), 512, GEMM_SMEM_BYTES>>>(
        p_ln, p_wup, nullptr, nullptr, nullptr, p_up, TOTAL, FDIM, DIM);
    // sigmoid gate (fp16 out)
    int n2 = (TOTAL * FDIM) / 2;
    gate_kernel<<<(n2 + 255) / 256, 256>>>((__half2*)p_gate, (const __half2*)p_up, n2);
    // down projection + residual -> output (fp32)
    gemm_f16_kernel<<<dim3(DIM / 256, TOTAL / 128), 512, GEMM_SMEM_BYTES>>>(
        p_gate, p_wdown, nullptr, p_h2, out, nullptr, TOTAL, DIM, FDIM);
}

// round 9
// speedup vs baseline: 1.5256x; 1.5256x over previous
#include <cuda_runtime.h>
#include <cuda_fp16.h>
#include <cstdint>

#define TOTAL   9216
#define DIM     2048
#define HEADS   16
#define HD      128
#define FDIM    8192
#define QKV3    6144

// ---------------- scratch (device globals: allocation-free) ----------------
__device__ __half g_ln  [(size_t)TOTAL * DIM];
__device__ float  g_qkv [(size_t)TOTAL * QKV3];
__device__ __half g_attn[(size_t)TOTAL * DIM];
__device__ float  g_h2  [(size_t)TOTAL * DIM];
__device__ __half g_gate[(size_t)TOTAL * FDIM];
__device__ __half g_up  [(size_t)TOTAL * FDIM];
// fp16 weight copies
__device__ __half g_wqkv [(size_t)QKV3 * DIM];
__device__ __half g_wout [(size_t)DIM * DIM];
__device__ __half g_wgate[(size_t)FDIM * DIM];
__device__ __half g_wup  [(size_t)FDIM * DIM];
__device__ __half g_wdown[(size_t)DIM * FDIM];

__device__ const int c_seqlen[8] = {512, 1024, 2048, 768, 1536, 896, 1280, 1152};

// ---------------- helpers ----------------
__device__ __forceinline__ uint32_t f2tf32(float x) {
    uint32_t r;
    asm("cvt.rna.tf32.f32 %0, %1;" : "=r"(r) : "f"(x));
    return r;
}

__device__ __forceinline__ void mma_tf32(float* c, const uint32_t* a, const uint32_t* b) {
    asm("mma.sync.aligned.m16n8k8.row.col.f32.tf32.tf32.f32 "
        "{%0,%1,%2,%3},{%4,%5,%6,%7},{%8,%9},{%0,%1,%2,%3};"
        : "+f"(c[0]), "+f"(c[1]), "+f"(c[2]), "+f"(c[3])
        : "r"(a[0]), "r"(a[1]), "r"(a[2]), "r"(a[3]), "r"(b[0]), "r"(b[1]));
}

__device__ __forceinline__ void mma_f16(float* c, const uint32_t* a, const uint32_t* b) {
    asm("mma.sync.aligned.m16n8k16.row.col.f32.f16.f16.f32 "
        "{%0,%1,%2,%3},{%4,%5,%6,%7},{%8,%9},{%0,%1,%2,%3};"
        : "+f"(c[0]), "+f"(c[1]), "+f"(c[2]), "+f"(c[3])
        : "r"(a[0]), "r"(a[1]), "r"(a[2]), "r"(a[3]), "r"(b[0]), "r"(b[1]));
}

__device__ __forceinline__ void ldsm_x4(uint32_t* r, uint32_t addr) {
    asm volatile("ldmatrix.sync.aligned.m8n8.x4.shared.b16 {%0,%1,%2,%3}, [%4];"
        : "=r"(r[0]), "=r"(r[1]), "=r"(r[2]), "=r"(r[3]) : "r"(addr));
}

__device__ __forceinline__ void cp_async16(void* smem_dst, const void* gmem_src) {
    uint32_t s = (uint32_t)__cvta_generic_to_shared(smem_dst);
    asm volatile("cp.async.cg.shared.global [%0], [%1], 16;" :: "r"(s), "l"(gmem_src));
}
__device__ __forceinline__ void cp_commit() {
    asm volatile("cp.async.commit_group;");
}

// ================= fp16 GEMM =================
// C[M,N] = A[M,K] * B[N,K]^T (+bias)(+resid), A,B fp16, accum fp32.
// 128x128 tile, 256 threads (8 warps as 2x4, warp tile 64x32), K-chunk 64,
// 3-stage cp.async pipeline, ONE __syncthreads per chunk (prefetch-after-barrier:
// the top barrier proves all warps finished compute(i-1), freeing stage (i+2)%3).
// Stride 72 halves (144B rows): conflict-free LDSM. 2 CTAs/SM.
#define HSTRIDE 72
#define A_HALFS (128 * HSTRIDE)
#define STAGE_HALFS (2 * A_HALFS)
#define GEMM_SMEM_BYTES (3 * STAGE_HALFS * 2)

__device__ __forceinline__ void h_load_stage(const __half* __restrict__ Ab,
                                             const __half* __restrict__ Bb,
                                             int K, __half* As, __half* Bs, int tid)
{
    #pragma unroll
    for (int j = 0; j < 4; j++) {
        int id = tid + j * 256;
        int r = id >> 3, g = (id & 7) << 3;     // 8 halves = 16B per group
        cp_async16(As + r * HSTRIDE + g, Ab + (size_t)r * K + g);
        cp_async16(Bs + r * HSTRIDE + g, Bb + (size_t)r * K + g);
    }
}

__global__ __launch_bounds__(256, 2) void gemm_f16_kernel(
    const __half* __restrict__ A, const __half* __restrict__ B,
    const float* __restrict__ bias, const float* __restrict__ resid,
    float* __restrict__ Cf, __half* __restrict__ Ch, int M, int N, int K)
{
    extern __shared__ __half hsm[];
    const uint32_t smemBase = (uint32_t)__cvta_generic_to_shared(hsm);

    const int tid  = threadIdx.x;
    const int lane = tid & 31, warp = tid >> 5;
    const int lq = lane >> 2, lr = lane & 3;
    const int wm = (warp >> 2) * 64, wn = (warp & 3) * 32;
    const int bm = blockIdx.y * 128, bn = blockIdx.x * 128;

    // ldmatrix lane mapping: tr = row-in-8, th = matrix row-half, tq = k-half
    const int tr = lane & 7, th = (lane >> 3) & 1, tq = lane >> 4;
    const uint32_t aoff = (uint32_t)(((wm + tr + th * 8) * HSTRIDE + tq * 8) * 2);
    const uint32_t boff = (uint32_t)(((wn + tr + th * 8) * HSTRIDE + tq * 8) * 2);

    float acc[4][4][4];
    #pragma unroll
    for (int mf = 0; mf < 4; mf++)
        #pragma unroll
        for (int nf = 0; nf < 4; nf++)
            #pragma unroll
            for (int e = 0; e < 4; e++) acc[mf][nf][e] = 0.f;

    const __half* Abase = A + (size_t)bm * K;
    const __half* Bbase = B + (size_t)bn * K;
    const int nk = K >> 6;

    // prologue: chunks 0,1 into stages 0,1
    #pragma unroll
    for (int s = 0; s < 2; s++) {
        __half* As = hsm + s * STAGE_HALFS;
        __half* Bs = As + A_HALFS;
        h_load_stage(Abase + s * 64, Bbase + s * 64, K, As, Bs, tid);
        cp_commit();
    }

    for (int i = 0; i < nk; i++) {
        // chunk i is complete after this wait (<=1 newer group outstanding)
        asm volatile("cp.async.wait_group 1;");
        __syncthreads();   // data visible to all; also proves compute(i-1) done by all

        // prefetch chunk i+2 into stage (i+2)%3 (== (i-1)%3, free after barrier)
        if (i + 2 < nk) {
            const int sd = (i + 2) % 3;
            __half* Ad = hsm + sd * STAGE_HALFS;
            __half* Bd = Ad + A_HALFS;
            h_load_stage(Abase + (i + 2) * 64, Bbase + (i + 2) * 64, K, Ad, Bd, tid);
        }
        cp_commit();   // unconditional: keeps group accounting exact at the tail

        const int st = i % 3;
        const uint32_t stOff = smemBase + (uint32_t)(st * STAGE_HALFS * 2);
        const uint32_t aBase = stOff + aoff;
        const uint32_t bBase = stOff + (uint32_t)(A_HALFS * 2) + boff;

        #pragma unroll
        for (int ks = 0; ks < 4; ks++) {
            const uint32_t kOff = (uint32_t)(ks * 32);   // 16 halves
            uint32_t af[4][4];
            #pragma unroll
            for (int mf = 0; mf < 4; mf++)
                ldsm_x4(af[mf], aBase + (uint32_t)(mf * 16 * HSTRIDE * 2) + kOff);
            uint32_t b0[4], b1[4];
            ldsm_x4(b0, bBase + kOff);
            ldsm_x4(b1, bBase + (uint32_t)(16 * HSTRIDE * 2) + kOff);
            uint32_t bf[4][2] = {{b0[0], b0[2]}, {b0[1], b0[3]},
                                 {b1[0], b1[2]}, {b1[1], b1[3]}};
            #pragma unroll
            for (int mf = 0; mf < 4; mf++)
                #pragma unroll
                for (int nf = 0; nf < 4; nf++)
                    mma_f16(acc[mf][nf], af[mf], bf[nf]);
        }
    }

    // epilogue
    #pragma unroll
    for (int mf = 0; mf < 4; mf++) {
        #pragma unroll
        for (int nf = 0; nf < 4; nf++) {
            int r0 = bm + wm + mf * 16 + lq;
            int c0 = bn + wn + nf * 8 + lr * 2;
            float b0 = 0.f, b1 = 0.f;
            if (bias) { b0 = bias[c0]; b1 = bias[c0 + 1]; }
            float2 v0 = make_float2(acc[mf][nf][0] + b0, acc[mf][nf][1] + b1);
            float2 v1 = make_float2(acc[mf][nf][2] + b0, acc[mf][nf][3] + b1);
            if (resid) {
                float2 ra = *reinterpret_cast<const float2*>(resid + (size_t)r0 * N + c0);
                float2 rb = *reinterpret_cast<const float2*>(resid + (size_t)(r0 + 8) * N + c0);
                v0.x += ra.x; v0.y += ra.y;
                v1.x += rb.x; v1.y += rb.y;
            }
            if (Ch) {
                *reinterpret_cast<__half2*>(Ch + (size_t)r0 * N + c0) =
                    __floats2half2_rn(v0.x, v0.y);
                *reinterpret_cast<__half2*>(Ch + (size_t)(r0 + 8) * N + c0) =
                    __floats2half2_rn(v1.x, v1.y);
            } else {
                *reinterpret_cast<float2*>(Cf + (size_t)r0 * N + c0) = v0;
                *reinterpret_cast<float2*>(Cf + (size_t)(r0 + 8) * N + c0) = v1;
            }
        }
    }
}

// ---------------- weight convert: fp32 -> fp16 ----------------
__global__ __launch_bounds__(256) void cvtw_kernel(const float4* __restrict__ in,
                                                   __half2* __restrict__ out, int n4)
{
    int i = blockIdx.x * blockDim.x + threadIdx.x;
    if (i < n4) {
        float4 v = in[i];
        out[2 * i]     = __floats2half2_rn(v.x, v.y);
        out[2 * i + 1] = __floats2half2_rn(v.z, v.w);
    }
}

// ---------------- RMSNorm (fp32 in, fp16 out) ----------------
__global__ __launch_bounds__(256) void rmsnorm_kernel(const float* __restrict__ x,
                                                      const float* __restrict__ w,
                                                      __half* __restrict__ y)
{
    int row = blockIdx.x;
    const float4* xr = reinterpret_cast<const float4*>(x + (size_t)row * DIM);
    __half2*      yr = reinterpret_cast<__half2*>(y + (size_t)row * DIM);
    const float4* wr = reinterpret_cast<const float4*>(w);
    int tid = threadIdx.x;

    float4 v0 = xr[tid];
    float4 v1 = xr[tid + 256];
    float ss = v0.x*v0.x + v0.y*v0.y + v0.z*v0.z + v0.w*v0.w
             + v1.x*v1.x + v1.y*v1.y + v1.z*v1.z + v1.w*v1.w;
    #pragma unroll
    for (int o = 16; o; o >>= 1) ss += __shfl_xor_sync(0xffffffffu, ss, o);

    __shared__ float red[8];
    __shared__ float stot;
    if ((tid & 31) == 0) red[tid >> 5] = ss;
    __syncthreads();
    if (tid == 0) {
        float t = 0.f;
        #pragma unroll
        for (int i = 0; i < 8; i++) t += red[i];
        stot = rsqrtf(t * (1.0f / (float)DIM) + 1e-6f);
    }
    __syncthreads();
    float r = stot;

    float4 w0 = wr[tid], w1 = wr[tid + 256];
    yr[2 * tid]             = __floats2half2_rn(v0.x*r*w0.x, v0.y*r*w0.y);
    yr[2 * tid + 1]         = __floats2half2_rn(v0.z*r*w0.z, v0.w*r*w0.w);
    yr[2 * (tid + 256)]     = __floats2half2_rn(v1.x*r*w1.x, v1.y*r*w1.y);
    yr[2 * (tid + 256) + 1] = __floats2half2_rn(v1.z*r*w1.z, v1.w*r*w1.w);
}

// ---------------- Flash attention (tf32 mma; qkv fp32 in, fp16 out) ----------------
#define Q_STRIDE 132
#define K_STRIDE 132
#define V_STRIDE 136
#define LOG2E 1.4426950408889634f

#define ATTN_SMEM_BYTES ((128*Q_STRIDE + 2*64*K_STRIDE + 2*64*V_STRIDE) * 4)

__global__ __launch_bounds__(256) void attn_kernel(const float* __restrict__ qkv,
                                                   __half* __restrict__ out)
{
    extern __shared__ char asm_base[];
    uint32_t* Qs   = reinterpret_cast<uint32_t*>(asm_base);
    float*    Kraw = reinterpret_cast<float*>(asm_base) + 128 * Q_STRIDE;
    float*    Vraw = Kraw + 2 * 64 * K_STRIDE;

    const int tile = blockIdx.x;
    const int h    = blockIdx.y;

    int seq_start = 0, q0 = 0;
    {
        int acc = 0, start = 0;
        #pragma unroll
        for (int s = 0; s < 8; s++) {
            int nt = c_seqlen[s] >> 7;
            if (tile >= acc && tile < acc + nt) {
                seq_start = start; q0 = (tile - acc) << 7;
            }
            acc += nt; start += c_seqlen[s];
        }
    }

    const int tid = threadIdx.x, lane = tid & 31, warp = tid >> 5;
    const int lq = lane >> 2, lr = lane & 3;
    const int nkv = (q0 >> 6) + 2;

    const size_t kv_row0 = (size_t)seq_start * QKV3 + DIM + (size_t)h * HD;

    #pragma unroll
    for (int t = 0; t < 2; t++) {
        float* Kd = Kraw + (t & 1) * (64 * K_STRIDE);
        float* Vd = Vraw + (t & 1) * (64 * V_STRIDE);
        const float* kb = qkv + kv_row0 + (size_t)(t * 64) * QKV3;
        #pragma unroll
        for (int j = 0; j < 8; j++) {
            int i = tid + j * 256;
            int r = i >> 5, dg = (i & 31) << 2;
            cp_async16(Kd + r * K_STRIDE + dg, kb + (size_t)r * QKV3 + dg);
            cp_async16(Vd + r * V_STRIDE + dg, kb + (size_t)r * QKV3 + DIM + dg);
        }
        cp_commit();
    }

    {
        const size_t qbase = (size_t)(seq_start + q0) * QKV3 + (size_t)h * HD;
        #pragma unroll
        for (int j = 0; j < 16; j++) {
            int i = tid + j * 256;
            int r = i >> 5, dg = (i & 31) << 2;
            float4 v = *reinterpret_cast<const float4*>(qkv + qbase + (size_t)r * QKV3 + dg);
            uint4 p;
            p.x = f2tf32(v.x); p.y = f2tf32(v.y); p.z = f2tf32(v.z); p.w = f2tf32(v.w);
            *reinterpret_cast<uint4*>(&Qs[r * Q_STRIDE + dg]) = p;
        }
    }

    float oacc[16][4];
    #pragma unroll
    for (int nf = 0; nf < 16; nf++)
        #pragma unroll
        for (int e = 0; e < 4; e++) oacc[nf][e] = 0.f;
    float m0 = -1e30f, m1 = -1e30f, l0 = 0.f, l1 = 0.f;
    const float scale = 0.08838834764831845f;

    const int qbase_warp = q0 + warp * 16;
    const int srcA = (lane & ~3) | (lr >> 1);
    const int srcB = srcA + 2;

    for (int t = 0; t < nkv; t++) {
        asm volatile("cp.async.wait_group 1;");
        __syncthreads();

        const int j0 = t << 6;
        const float* Kb = Kraw + (t & 1) * (64 * K_STRIDE);
        const float* Vb = Vraw + (t & 1) * (64 * V_STRIDE);
        const bool skipw = (j0 > qbase_warp + 15);

        if (!skipw) {
            float sacc[8][4];
            #pragma unroll
            for (int nf = 0; nf < 8; nf++)
                #pragma unroll
                for (int e = 0; e < 4; e++) sacc[nf][e] = 0.f;

            #pragma unroll
            for (int ks = 0; ks < 16; ks++) {
                int kk = ks * 8;
                uint32_t af[4];
                int mrow = warp * 16 + lq;
                af[0] = Qs[mrow * Q_STRIDE + kk + lr];
                af[1] = Qs[(mrow + 8) * Q_STRIDE + kk + lr];
                af[2] = Qs[mrow * Q_STRIDE + kk + lr + 4];
                af[3] = Qs[(mrow + 8) * Q_STRIDE + kk + lr + 4];
                #pragma unroll
                for (int nf = 0; nf < 8; nf++) {
                    uint32_t bf[2];
                    int ncol = nf * 8 + lq;
                    bf[0] = f2tf32(Kb[ncol * K_STRIDE + kk + lr]);
                    bf[1] = f2tf32(Kb[ncol * K_STRIDE + kk + lr + 4]);
                    mma_tf32(sacc[nf], af, bf);
                }
            }

            const bool diag = (j0 + 63 > qbase_warp);
            const int qr0 = qbase_warp + lq;
            const int qr1 = qr0 + 8;
            float mx0 = -1e30f, mx1 = -1e30f;
            #pragma unroll
            for (int nf = 0; nf < 8; nf++) {
                #pragma unroll
                for (int e = 0; e < 4; e++) {
                    float s = sacc[nf][e] * scale;
                    if (diag) {
                        int kc = j0 + nf * 8 + lr * 2 + (e & 1);
                        int qr = (e < 2) ? qr0 : qr1;
                        if (kc > qr) s = -1e30f;
                    }
                    sacc[nf][e] = s;
                }
                mx0 = fmaxf(mx0, fmaxf(sacc[nf][0], sacc[nf][1]));
                mx1 = fmaxf(mx1, fmaxf(sacc[nf][2], sacc[nf][3]));
            }
            mx0 = fmaxf(mx0, __shfl_xor_sync(0xffffffffu, mx0, 1));
            mx0 = fmaxf(mx0, __shfl_xor_sync(0xffffffffu, mx0, 2));
            mx1 = fmaxf(mx1, __shfl_xor_sync(0xffffffffu, mx1, 1));
            mx1 = fmaxf(mx1, __shfl_xor_sync(0xffffffffu, mx1, 2));

            float mn0 = fmaxf(m0, mx0), mn1 = fmaxf(m1, mx1);
            float c0 = exp2f((m0 - mn0) * LOG2E), c1 = exp2f((m1 - mn1) * LOG2E);
            float s0 = 0.f, s1 = 0.f;
            uint32_t pk[8][4];
            #pragma unroll
            for (int nf = 0; nf < 8; nf++) {
                float p0 = exp2f((sacc[nf][0] - mn0) * LOG2E);
                float p1 = exp2f((sacc[nf][1] - mn0) * LOG2E);
                float p2 = exp2f((sacc[nf][2] - mn1) * LOG2E);
                float p3 = exp2f((sacc[nf][3] - mn1) * LOG2E);
                s0 += p0 + p1; s1 += p2 + p3;
                pk[nf][0] = f2tf32(p0);
                pk[nf][1] = f2tf32(p1);
                pk[nf][2] = f2tf32(p2);
                pk[nf][3] = f2tf32(p3);
            }
            s0 += __shfl_xor_sync(0xffffffffu, s0, 1);
            s0 += __shfl_xor_sync(0xffffffffu, s0, 2);
            s1 += __shfl_xor_sync(0xffffffffu, s1, 1);
            s1 += __shfl_xor_sync(0xffffffffu, s1, 2);
            l0 = l0 * c0 + s0;
            l1 = l1 * c1 + s1;
            m0 = mn0; m1 = mn1;
            #pragma unroll
            for (int nf = 0; nf < 16; nf++) {
                oacc[nf][0] *= c0; oacc[nf][1] *= c0;
                oacc[nf][2] *= c1; oacc[nf][3] *= c1;
            }

            #pragma unroll
            for (int ks = 0; ks < 8; ks++) {
                uint32_t af[4];
                {
                    uint32_t u0 = __shfl_sync(0xffffffffu, pk[ks][0], srcA);
                    uint32_t u1 = __shfl_sync(0xffffffffu, pk[ks][1], srcA);
                    uint32_t u2 = __shfl_sync(0xffffffffu, pk[ks][2], srcA);
                    uint32_t u3 = __shfl_sync(0xffffffffu, pk[ks][3], srcA);
                    uint32_t v0 = __shfl_sync(0xffffffffu, pk[ks][0], srcB);
                    uint32_t v1 = __shfl_sync(0xffffffffu, pk[ks][1], srcB);
                    uint32_t v2 = __shfl_sync(0xffffffffu, pk[ks][2], srcB);
                    uint32_t v3 = __shfl_sync(0xffffffffu, pk[ks][3], srcB);
                    af[0] = (lr & 1) ? u1 : u0;
                    af[1] = (lr & 1) ? u3 : u2;
                    af[2] = (lr & 1) ? v1 : v0;
                    af[3] = (lr & 1) ? v3 : v2;
                }
                int kk = ks * 8;
                #pragma unroll
                for (int nf = 0; nf < 16; nf++) {
                    uint32_t bf[2];
                    int ncol = nf * 8 + lq;
                    bf[0] = f2tf32(Vb[(kk + lr) * V_STRIDE + ncol]);
                    bf[1] = f2tf32(Vb[(kk + lr + 4) * V_STRIDE + ncol]);
                    mma_tf32(oacc[nf], af, bf);
                }
            }
        }

        __syncthreads();

        if (t + 2 < nkv) {
            float* Kd = Kraw + (t & 1) * (64 * K_STRIDE);
            float* Vd = Vraw + (t & 1) * (64 * V_STRIDE);
            const float* kb = qkv + kv_row0 + (size_t)((t + 2) * 64) * QKV3;
            #pragma unroll
            for (int j = 0; j < 8; j++) {
                int i = tid + j * 256;
                int r = i >> 5, dg = (i & 31) << 2;
                cp_async16(Kd + r * K_STRIDE + dg, kb + (size_t)r * QKV3 + dg);
                cp_async16(Vd + r * V_STRIDE + dg, kb + (size_t)r * QKV3 + DIM + dg);
            }
        }
        cp_commit();
    }

    // epilogue -> fp16 (feeds out_proj fp16 GEMM)
    float inv0 = 1.f / l0, inv1 = 1.f / l1;
    int t0 = seq_start + q0 + warp * 16 + lq;
    __half* ob = out + (size_t)t0 * DIM + (size_t)h * HD;
    #pragma unroll
    for (int nf = 0; nf < 16; nf++) {
        int c = nf * 8 + lr * 2;
        *reinterpret_cast<__half2*>(ob + c) =
            __floats2half2_rn(oacc[nf][0] * inv0, oacc[nf][1] * inv0);
        *reinterpret_cast<__half2*>(ob + (size_t)8 * DIM + c) =
            __floats2half2_rn(oacc[nf][2] * inv1, oacc[nf][3] * inv1);
    }
}

// ---------------- sigmoid gate: g = fp16(sigmoid(g) * u) ----------------
__global__ __launch_bounds__(256) void gate_kernel(__half2* __restrict__ g,
                                                   const __half2* __restrict__ u, int n2)
{
    int i = blockIdx.x * blockDim.x + threadIdx.x;
    if (i < n2) {
        float2 gv = __half22float2(g[i]);
        float2 uv = __half22float2(u[i]);
        gv.x = uv.x / (1.f + __expf(-gv.x));
        gv.y = uv.y / (1.f + __expf(-gv.y));
        g[i] = __floats2half2_rn(gv.x, gv.y);
    }
}

// ---------------- launch ----------------
extern "C" void kernel_launch(void* const* d_in, const int* in_sizes, int n_in,
                              void* d_out, int out_size)
{
    const float* hidden     = (const float*)d_in[0];
    const float* ln1_w      = (const float*)d_in[1];
    const float* ln2_w      = (const float*)d_in[2];
    const float* in_proj_w  = (const float*)d_in[3];
    const float* in_proj_b  = (const float*)d_in[4];
    const float* out_proj_w = (const float*)d_in[5];
    const float* out_proj_b = (const float*)d_in[6];
    const float* gate_w     = (const float*)d_in[7];
    const float* up_w       = (const float*)d_in[8];
    const float* down_w     = (const float*)d_in[9];
    float* out = (float*)d_out;

    __half *p_ln, *p_attn, *p_gate, *p_up;
    float  *p_qkv, *p_h2;
    __half *p_wqkv, *p_wout, *p_wgate, *p_wup, *p_wdown;
    cudaGetSymbolAddress((void**)&p_ln,    g_ln);
    cudaGetSymbolAddress((void**)&p_qkv,   g_qkv);
    cudaGetSymbolAddress((void**)&p_attn,  g_attn);
    cudaGetSymbolAddress((void**)&p_h2,    g_h2);
    cudaGetSymbolAddress((void**)&p_gate,  g_gate);
    cudaGetSymbolAddress((void**)&p_up,    g_up);
    cudaGetSymbolAddress((void**)&p_wqkv,  g_wqkv);
    cudaGetSymbolAddress((void**)&p_wout,  g_wout);
    cudaGetSymbolAddress((void**)&p_wgate, g_wgate);
    cudaGetSymbolAddress((void**)&p_wup,   g_wup);
    cudaGetSymbolAddress((void**)&p_wdown, g_wdown);

    cudaFuncSetAttribute((const void*)gemm_f16_kernel,
                         cudaFuncAttributeMaxDynamicSharedMemorySize, GEMM_SMEM_BYTES);
    cudaFuncSetAttribute((const void*)attn_kernel,
                         cudaFuncAttributeMaxDynamicSharedMemorySize, ATTN_SMEM_BYTES);

    int n4;
    // launch 0: qkv weight conversion
    n4 = (QKV3 * DIM) / 4;
    cvtw_kernel<<<(n4 + 255) / 256, 256>>>((const float4*)in_proj_w, (__half2*)p_wqkv, n4);
    // launch 1: rmsnorm1 (fp16 out)
    rmsnorm_kernel<<<TOTAL, 256>>>(hidden, ln1_w, p_ln);
    // launch 2: out-proj weight conversion
    n4 = (DIM * DIM) / 4;
    cvtw_kernel<<<(n4 + 255) / 256, 256>>>((const float4*)out_proj_w, (__half2*)p_wout, n4);
    // launch 3: qkv projection (ncu capture slot)
    gemm_f16_kernel<<<dim3(QKV3 / 128, TOTAL / 128), 256, GEMM_SMEM_BYTES>>>(
        p_ln, p_wqkv, in_proj_b, nullptr, p_qkv, nullptr, TOTAL, QKV3, DIM);
    // launch 4: attention (fp16 out)
    attn_kernel<<<dim3(TOTAL / 128, HEADS), 256, ATTN_SMEM_BYTES>>>(p_qkv, p_attn);
    // launch 5: out projection + residual (fp32 out)
    gemm_f16_kernel<<<dim3(DIM / 128, TOTAL / 128), 256, GEMM_SMEM_BYTES>>>(
        p_attn, p_wout, out_proj_b, hidden, p_h2, nullptr, TOTAL, DIM, DIM);
    // launch 6: rmsnorm2 (fp16 out)
    rmsnorm_kernel<<<TOTAL, 256>>>(p_h2, ln2_w, p_ln);
    // launches 7,8: gate & up weight conversions
    n4 = (FDIM * DIM) / 4;
    cvtw_kernel<<<(n4 + 255) / 256, 256>>>((const float4*)gate_w, (__half2*)p_wgate, n4);
    cvtw_kernel<<<(n4 + 255) / 256, 256>>>((const float4*)up_w, (__half2*)p_wup, n4);
    // launches 9,10: gate & up projections (fp16 out)
    gemm_f16_kernel<<<dim3(FDIM / 128, TOTAL / 128), 256, GEMM_SMEM_BYTES>>>(
        p_ln, p_wgate, nullptr, nullptr, nullptr, p_gate, TOTAL, FDIM, DIM);
    gemm_f16_kernel<<<dim3(FDIM / 128, TOTAL / 128), 256, GEMM_SMEM_BYTES>>>(
        p_ln, p_wup, nullptr, nullptr, nullptr, p_up, TOTAL, FDIM, DIM);
    // launch 11: down weight conversion
    cvtw_kernel<<<(n4 + 255) / 256, 256>>>((const float4*)down_w, (__half2*)p_wdown, n4);
    // launch 12: sigmoid gate (fp16 out)
    int n2 = (TOTAL * FDIM) / 2;
    gate_kernel<<<(n2 + 255) / 256, 256>>>((__half2*)p_gate, (const __half2*)p_up, n2);
    // launch 13: down projection + residual -> output (fp32)
    gemm_f16_kernel<<<dim3(DIM / 128, TOTAL / 128), 256, GEMM_SMEM_BYTES>>>(
        p_gate, p_wdown, nullptr, p_h2, out, nullptr, TOTAL, DIM, FDIM);
}

// round 10
// speedup vs baseline: 1.8134x; 1.1887x over previous
#include <cuda_runtime.h>
#include <cuda_fp16.h>
#include <cstdint>

#define TOTAL   9216
#define DIM     2048
#define HEADS   16
#define HD      128
#define FDIM    8192
#define QKV3    6144

// ---------------- scratch (device globals: allocation-free) ----------------
__device__ __half g_ln  [(size_t)TOTAL * DIM];
__device__ float  g_qkv [(size_t)TOTAL * QKV3];
__device__ __half g_attn[(size_t)TOTAL * DIM];
__device__ float  g_h2  [(size_t)TOTAL * DIM];
__device__ __half g_gate[(size_t)TOTAL * FDIM];
__device__ __half g_up  [(size_t)TOTAL * FDIM];
// fp16 weight copies
__device__ __half g_wqkv [(size_t)QKV3 * DIM];
__device__ __half g_wout [(size_t)DIM * DIM];
__device__ __half g_wgate[(size_t)FDIM * DIM];
__device__ __half g_wup  [(size_t)FDIM * DIM];
__device__ __half g_wdown[(size_t)DIM * FDIM];

__device__ const int c_seqlen[8] = {512, 1024, 2048, 768, 1536, 896, 1280, 1152};

// ---------------- helpers ----------------
__device__ __forceinline__ uint32_t f2tf32(float x) {
    uint32_t r;
    asm("cvt.rna.tf32.f32 %0, %1;" : "=r"(r) : "f"(x));
    return r;
}

__device__ __forceinline__ void mma_tf32(float* c, const uint32_t* a, const uint32_t* b) {
    asm("mma.sync.aligned.m16n8k8.row.col.f32.tf32.tf32.f32 "
        "{%0,%1,%2,%3},{%4,%5,%6,%7},{%8,%9},{%0,%1,%2,%3};"
        : "+f"(c[0]), "+f"(c[1]), "+f"(c[2]), "+f"(c[3])
        : "r"(a[0]), "r"(a[1]), "r"(a[2]), "r"(a[3]), "r"(b[0]), "r"(b[1]));
}

__device__ __forceinline__ void mma_f16(float* c, const uint32_t* a, const uint32_t* b) {
    asm("mma.sync.aligned.m16n8k16.row.col.f32.f16.f16.f32 "
        "{%0,%1,%2,%3},{%4,%5,%6,%7},{%8,%9},{%0,%1,%2,%3};"
        : "+f"(c[0]), "+f"(c[1]), "+f"(c[2]), "+f"(c[3])
        : "r"(a[0]), "r"(a[1]), "r"(a[2]), "r"(a[3]), "r"(b[0]), "r"(b[1]));
}

__device__ __forceinline__ void ldsm_x4(uint32_t* r, uint32_t addr) {
    asm volatile("ldmatrix.sync.aligned.m8n8.x4.shared.b16 {%0,%1,%2,%3}, [%4];"
        : "=r"(r[0]), "=r"(r[1]), "=r"(r[2]), "=r"(r[3]) : "r"(addr));
}

__device__ __forceinline__ void cp_async16(void* smem_dst, const void* gmem_src) {
    uint32_t s = (uint32_t)__cvta_generic_to_shared(smem_dst);
    asm volatile("cp.async.cg.shared.global [%0], [%1], 16;" :: "r"(s), "l"(gmem_src));
}
__device__ __forceinline__ void cp_commit() {
    asm volatile("cp.async.commit_group;");
}

// mbarrier primitives (plain forms: proven to compile for compute_103 in round 3)
__device__ __forceinline__ void mbar_init(uint32_t addr, uint32_t count) {
    asm volatile("mbarrier.init.shared.b64 [%0], %1;" :: "r"(addr), "r"(count) : "memory");
}
__device__ __forceinline__ void mbar_arrive(uint32_t addr) {
    asm volatile("mbarrier.arrive.shared.b64 _, [%0];" :: "r"(addr) : "memory");
}
__device__ __forceinline__ void cp_mbar_arrive(uint32_t addr) {
    asm volatile("cp.async.mbarrier.arrive.noinc.shared.b64 [%0];" :: "r"(addr) : "memory");
}
__device__ __forceinline__ void mbar_wait(uint32_t addr, uint32_t parity) {
    asm volatile(
        "{\n\t.reg .pred P;\n\t"
        "W%=:\n\t"
        "mbarrier.try_wait.parity.shared.b64 P, [%0], %1;\n\t"
        "@!P bra W%=;\n\t}"
        :: "r"(addr), "r"(parity) : "memory");
}

// ================= fp16 GEMM, barrier-free mbarrier pipeline =================
// C[M,N] = A[M,K] * B[N,K]^T (+bias)(+resid), A,B fp16, accum fp32.
// 128x128 tile, 256 threads (8 warps as 2x4, warp tile 64x32), K-chunk 64,
// 3-stage cp.async pipeline, NO __syncthreads in mainloop: per-stage mbarriers
// (full: cp.async.mbarrier.arrive from 256 threads; empty: arrive after consume).
// Warps free-run with ~2 chunks skew -> tensor pipe stays fed. 2 CTAs/SM.
#define HSTRIDE 72
#define A_HALFS (128 * HSTRIDE)
#define STAGE_HALFS (2 * A_HALFS)
#define STAGE_BYTES (STAGE_HALFS * 2)
#define GEMM_SMEM_BYTES (3 * STAGE_BYTES + 64)

__device__ __forceinline__ void h_load_stage(const __half* __restrict__ Ab,
                                             const __half* __restrict__ Bb,
                                             int K, __half* As, __half* Bs, int tid)
{
    #pragma unroll
    for (int j = 0; j < 4; j++) {
        int id = tid + j * 256;
        int r = id >> 3, g = (id & 7) << 3;     // 8 halves = 16B per group
        cp_async16(As + r * HSTRIDE + g, Ab + (size_t)r * K + g);
        cp_async16(Bs + r * HSTRIDE + g, Bb + (size_t)r * K + g);
    }
}

__global__ __launch_bounds__(256, 2) void gemm_f16_kernel(
    const __half* __restrict__ A, const __half* __restrict__ B,
    const float* __restrict__ bias, const float* __restrict__ resid,
    float* __restrict__ Cf, __half* __restrict__ Ch, int M, int N, int K)
{
    extern __shared__ __half hsm[];
    const uint32_t smemBase = (uint32_t)__cvta_generic_to_shared(hsm);

    const int tid  = threadIdx.x;
    const int lane = tid & 31, warp = tid >> 5;
    const int lq = lane >> 2, lr = lane & 3;
    const int wm = (warp >> 2) * 64, wn = (warp & 3) * 32;
    const int bm = blockIdx.y * 128, bn = blockIdx.x * 128;

    // ldmatrix lane mapping: tr = row-in-8, th = matrix row-half, tq = k-half
    const int tr = lane & 7, th = (lane >> 3) & 1, tq = lane >> 4;
    const uint32_t aoff = (uint32_t)(((wm + tr + th * 8) * HSTRIDE + tq * 8) * 2);
    const uint32_t boff = (uint32_t)(((wn + tr + th * 8) * HSTRIDE + tq * 8) * 2);

    // mbarriers after the 3 stage buffers: full[s]=+8s, empty[s]=+24+8s
    const uint32_t barB = smemBase + 3 * STAGE_BYTES;

    float acc[4][4][4];
    #pragma unroll
    for (int mf = 0; mf < 4; mf++)
        #pragma unroll
        for (int nf = 0; nf < 4; nf++)
            #pragma unroll
            for (int e = 0; e < 4; e++) acc[mf][nf][e] = 0.f;

    const __half* Abase = A + (size_t)bm * K;
    const __half* Bbase = B + (size_t)bn * K;
    const int nk = K >> 6;

    if (tid < 3) {
        mbar_init(barB + 8 * tid, 256);        // full[s]
        mbar_init(barB + 24 + 8 * tid, 256);   // empty[s]
    }
    __syncthreads();   // barriers visible before first cp.async arrive

    // prologue: produce chunks 0,1 into stages 0,1
    #pragma unroll
    for (int s = 0; s < 2; s++) {
        __half* As = hsm + s * STAGE_HALFS;
        __half* Bs = As + A_HALFS;
        h_load_stage(Abase + s * 64, Bbase + s * 64, K, As, Bs, tid);
        cp_mbar_arrive(barB + 8 * s);
    }

    for (int i = 0; i < nk; i++) {
        const int st = i % 3;
        // consume chunk i
        mbar_wait(barB + 8 * st, (uint32_t)((i / 3) & 1));

        const uint32_t stOff = smemBase + (uint32_t)(st * STAGE_BYTES);
        const uint32_t aBase = stOff + aoff;
        const uint32_t bBase = stOff + (uint32_t)(A_HALFS * 2) + boff;

        #pragma unroll
        for (int ks = 0; ks < 4; ks++) {
            const uint32_t kOff = (uint32_t)(ks * 32);   // 16 halves
            uint32_t af[4][4];
            #pragma unroll
            for (int mf = 0; mf < 4; mf++)
                ldsm_x4(af[mf], aBase + (uint32_t)(mf * 16 * HSTRIDE * 2) + kOff);
            uint32_t b0[4], b1[4];
            ldsm_x4(b0, bBase + kOff);
            ldsm_x4(b1, bBase + (uint32_t)(16 * HSTRIDE * 2) + kOff);
            uint32_t bf[4][2] = {{b0[0], b0[2]}, {b0[1], b0[3]},
                                 {b1[0], b1[2]}, {b1[1], b1[3]}};
            #pragma unroll
            for (int mf = 0; mf < 4; mf++)
                #pragma unroll
                for (int nf = 0; nf < 4; nf++)
                    mma_f16(acc[mf][nf], af[mf], bf[nf]);
        }
        mbar_arrive(barB + 24 + 8 * st);   // this thread done reading stage st

        // produce chunk i+2 into its buffer (freed once all consumed chunk i-1)
        const int c = i + 2;
        if (c < nk) {
            const int ps = c % 3;
            if (c >= 3)
                mbar_wait(barB + 24 + 8 * ps, (uint32_t)(((c / 3) - 1) & 1));
            __half* Ad = hsm + ps * STAGE_HALFS;
            __half* Bd = Ad + A_HALFS;
            h_load_stage(Abase + (size_t)c * 64, Bbase + (size_t)c * 64, K, Ad, Bd, tid);
            cp_mbar_arrive(barB + 8 * ps);
        }
    }

    // epilogue (registers only; no sync needed)
    #pragma unroll
    for (int mf = 0; mf < 4; mf++) {
        #pragma unroll
        for (int nf = 0; nf < 4; nf++) {
            int r0 = bm + wm + mf * 16 + lq;
            int c0 = bn + wn + nf * 8 + lr * 2;
            float b0 = 0.f, b1 = 0.f;
            if (bias) { b0 = bias[c0]; b1 = bias[c0 + 1]; }
            float2 v0 = make_float2(acc[mf][nf][0] + b0, acc[mf][nf][1] + b1);
            float2 v1 = make_float2(acc[mf][nf][2] + b0, acc[mf][nf][3] + b1);
            if (resid) {
                float2 ra = *reinterpret_cast<const float2*>(resid + (size_t)r0 * N + c0);
                float2 rb = *reinterpret_cast<const float2*>(resid + (size_t)(r0 + 8) * N + c0);
                v0.x += ra.x; v0.y += ra.y;
                v1.x += rb.x; v1.y += rb.y;
            }
            if (Ch) {
                *reinterpret_cast<__half2*>(Ch + (size_t)r0 * N + c0) =
                    __floats2half2_rn(v0.x, v0.y);
                *reinterpret_cast<__half2*>(Ch + (size_t)(r0 + 8) * N + c0) =
                    __floats2half2_rn(v1.x, v1.y);
            } else {
                *reinterpret_cast<float2*>(Cf + (size_t)r0 * N + c0) = v0;
                *reinterpret_cast<float2*>(Cf + (size_t)(r0 + 8) * N + c0) = v1;
            }
        }
    }
}

// ---------------- weight convert: fp32 -> fp16 ----------------
__global__ __launch_bounds__(256) void cvtw_kernel(const float4* __restrict__ in,
                                                   __half2* __restrict__ out, int n4)
{
    int i = blockIdx.x * blockDim.x + threadIdx.x;
    if (i < n4) {
        float4 v = in[i];
        out[2 * i]     = __floats2half2_rn(v.x, v.y);
        out[2 * i + 1] = __floats2half2_rn(v.z, v.w);
    }
}

// ---------------- RMSNorm (fp32 in, fp16 out) ----------------
__global__ __launch_bounds__(256) void rmsnorm_kernel(const float* __restrict__ x,
                                                      const float* __restrict__ w,
                                                      __half* __restrict__ y)
{
    int row = blockIdx.x;
    const float4* xr = reinterpret_cast<const float4*>(x + (size_t)row * DIM);
    __half2*      yr = reinterpret_cast<__half2*>(y + (size_t)row * DIM);
    const float4* wr = reinterpret_cast<const float4*>(w);
    int tid = threadIdx.x;

    float4 v0 = xr[tid];
    float4 v1 = xr[tid + 256];
    float ss = v0.x*v0.x + v0.y*v0.y + v0.z*v0.z + v0.w*v0.w
             + v1.x*v1.x + v1.y*v1.y + v1.z*v1.z + v1.w*v1.w;
    #pragma unroll
    for (int o = 16; o; o >>= 1) ss += __shfl_xor_sync(0xffffffffu, ss, o);

    __shared__ float red[8];
    __shared__ float stot;
    if ((tid & 31) == 0) red[tid >> 5] = ss;
    __syncthreads();
    if (tid == 0) {
        float t = 0.f;
        #pragma unroll
        for (int i = 0; i < 8; i++) t += red[i];
        stot = rsqrtf(t * (1.0f / (float)DIM) + 1e-6f);
    }
    __syncthreads();
    float r = stot;

    float4 w0 = wr[tid], w1 = wr[tid + 256];
    yr[2 * tid]             = __floats2half2_rn(v0.x*r*w0.x, v0.y*r*w0.y);
    yr[2 * tid + 1]         = __floats2half2_rn(v0.z*r*w0.z, v0.w*r*w0.w);
    yr[2 * (tid + 256)]     = __floats2half2_rn(v1.x*r*w1.x, v1.y*r*w1.y);
    yr[2 * (tid + 256) + 1] = __floats2half2_rn(v1.z*r*w1.z, v1.w*r*w1.w);
}

// ---------------- Flash attention (tf32 mma; qkv fp32 in, fp16 out) ----------------
#define Q_STRIDE 132
#define K_STRIDE 132
#define V_STRIDE 136
#define LOG2E 1.4426950408889634f

#define ATTN_SMEM_BYTES ((128*Q_STRIDE + 2*64*K_STRIDE + 2*64*V_STRIDE) * 4)

__global__ __launch_bounds__(256) void attn_kernel(const float* __restrict__ qkv,
                                                   __half* __restrict__ out)
{
    extern __shared__ char asm_base[];
    uint32_t* Qs   = reinterpret_cast<uint32_t*>(asm_base);
    float*    Kraw = reinterpret_cast<float*>(asm_base) + 128 * Q_STRIDE;
    float*    Vraw = Kraw + 2 * 64 * K_STRIDE;

    const int tile = blockIdx.x;
    const int h    = blockIdx.y;

    int seq_start = 0, q0 = 0;
    {
        int acc = 0, start = 0;
        #pragma unroll
        for (int s = 0; s < 8; s++) {
            int nt = c_seqlen[s] >> 7;
            if (tile >= acc && tile < acc + nt) {
                seq_start = start; q0 = (tile - acc) << 7;
            }
            acc += nt; start += c_seqlen[s];
        }
    }

    const int tid = threadIdx.x, lane = tid & 31, warp = tid >> 5;
    const int lq = lane >> 2, lr = lane & 3;
    const int nkv = (q0 >> 6) + 2;

    const size_t kv_row0 = (size_t)seq_start * QKV3 + DIM + (size_t)h * HD;

    #pragma unroll
    for (int t = 0; t < 2; t++) {
        float* Kd = Kraw + (t & 1) * (64 * K_STRIDE);
        float* Vd = Vraw + (t & 1) * (64 * V_STRIDE);
        const float* kb = qkv + kv_row0 + (size_t)(t * 64) * QKV3;
        #pragma unroll
        for (int j = 0; j < 8; j++) {
            int i = tid + j * 256;
            int r = i >> 5, dg = (i & 31) << 2;
            cp_async16(Kd + r * K_STRIDE + dg, kb + (size_t)r * QKV3 + dg);
            cp_async16(Vd + r * V_STRIDE + dg, kb + (size_t)r * QKV3 + DIM + dg);
        }
        cp_commit();
    }

    {
        const size_t qbase = (size_t)(seq_start + q0) * QKV3 + (size_t)h * HD;
        #pragma unroll
        for (int j = 0; j < 16; j++) {
            int i = tid + j * 256;
            int r = i >> 5, dg = (i & 31) << 2;
            float4 v = *reinterpret_cast<const float4*>(qkv + qbase + (size_t)r * QKV3 + dg);
            uint4 p;
            p.x = f2tf32(v.x); p.y = f2tf32(v.y); p.z = f2tf32(v.z); p.w = f2tf32(v.w);
            *reinterpret_cast<uint4*>(&Qs[r * Q_STRIDE + dg]) = p;
        }
    }

    float oacc[16][4];
    #pragma unroll
    for (int nf = 0; nf < 16; nf++)
        #pragma unroll
        for (int e = 0; e < 4; e++) oacc[nf][e] = 0.f;
    float m0 = -1e30f, m1 = -1e30f, l0 = 0.f, l1 = 0.f;
    const float scale = 0.08838834764831845f;

    const int qbase_warp = q0 + warp * 16;
    const int srcA = (lane & ~3) | (lr >> 1);
    const int srcB = srcA + 2;

    for (int t = 0; t < nkv; t++) {
        asm volatile("cp.async.wait_group 1;");
        __syncthreads();

        const int j0 = t << 6;
        const float* Kb = Kraw + (t & 1) * (64 * K_STRIDE);
        const float* Vb = Vraw + (t & 1) * (64 * V_STRIDE);
        const bool skipw = (j0 > qbase_warp + 15);

        if (!skipw) {
            float sacc[8][4];
            #pragma unroll
            for (int nf = 0; nf < 8; nf++)
                #pragma unroll
                for (int e = 0; e < 4; e++) sacc[nf][e] = 0.f;

            #pragma unroll
            for (int ks = 0; ks < 16; ks++) {
                int kk = ks * 8;
                uint32_t af[4];
                int mrow = warp * 16 + lq;
                af[0] = Qs[mrow * Q_STRIDE + kk + lr];
                af[1] = Qs[(mrow + 8) * Q_STRIDE + kk + lr];
                af[2] = Qs[mrow * Q_STRIDE + kk + lr + 4];
                af[3] = Qs[(mrow + 8) * Q_STRIDE + kk + lr + 4];
                #pragma unroll
                for (int nf = 0; nf < 8; nf++) {
                    uint32_t bf[2];
                    int ncol = nf * 8 + lq;
                    bf[0] = f2tf32(Kb[ncol * K_STRIDE + kk + lr]);
                    bf[1] = f2tf32(Kb[ncol * K_STRIDE + kk + lr + 4]);
                    mma_tf32(sacc[nf], af, bf);
                }
            }

            const bool diag = (j0 + 63 > qbase_warp);
            const int qr0 = qbase_warp + lq;
            const int qr1 = qr0 + 8;
            float mx0 = -1e30f, mx1 = -1e30f;
            #pragma unroll
            for (int nf = 0; nf < 8; nf++) {
                #pragma unroll
                for (int e = 0; e < 4; e++) {
                    float s = sacc[nf][e] * scale;
                    if (diag) {
                        int kc = j0 + nf * 8 + lr * 2 + (e & 1);
                        int qr = (e < 2) ? qr0 : qr1;
                        if (kc > qr) s = -1e30f;
                    }
                    sacc[nf][e] = s;
                }
                mx0 = fmaxf(mx0, fmaxf(sacc[nf][0], sacc[nf][1]));
                mx1 = fmaxf(mx1, fmaxf(sacc[nf][2], sacc[nf][3]));
            }
            mx0 = fmaxf(mx0, __shfl_xor_sync(0xffffffffu, mx0, 1));
            mx0 = fmaxf(mx0, __shfl_xor_sync(0xffffffffu, mx0, 2));
            mx1 = fmaxf(mx1, __shfl_xor_sync(0xffffffffu, mx1, 1));
            mx1 = fmaxf(mx1, __shfl_xor_sync(0xffffffffu, mx1, 2));

            float mn0 = fmaxf(m0, mx0), mn1 = fmaxf(m1, mx1);
            float c0 = exp2f((m0 - mn0) * LOG2E), c1 = exp2f((m1 - mn1) * LOG2E);
            float s0 = 0.f, s1 = 0.f;
            uint32_t pk[8][4];
            #pragma unroll
            for (int nf = 0; nf < 8; nf++) {
                float p0 = exp2f((sacc[nf][0] - mn0) * LOG2E);
                float p1 = exp2f((sacc[nf][1] - mn0) * LOG2E);
                float p2 = exp2f((sacc[nf][2] - mn1) * LOG2E);
                float p3 = exp2f((sacc[nf][3] - mn1) * LOG2E);
                s0 += p0 + p1; s1 += p2 + p3;
                pk[nf][0] = f2tf32(p0);
                pk[nf][1] = f2tf32(p1);
                pk[nf][2] = f2tf32(p2);
                pk[nf][3] = f2tf32(p3);
            }
            s0 += __shfl_xor_sync(0xffffffffu, s0, 1);
            s0 += __shfl_xor_sync(0xffffffffu, s0, 2);
            s1 += __shfl_xor_sync(0xffffffffu, s1, 1);
            s1 += __shfl_xor_sync(0xffffffffu, s1, 2);
            l0 = l0 * c0 + s0;
            l1 = l1 * c1 + s1;
            m0 = mn0; m1 = mn1;
            #pragma unroll
            for (int nf = 0; nf < 16; nf++) {
                oacc[nf][0] *= c0; oacc[nf][1] *= c0;
                oacc[nf][2] *= c1; oacc[nf][3] *= c1;
            }

            #pragma unroll
            for (int ks = 0; ks < 8; ks++) {
                uint32_t af[4];
                {
                    uint32_t u0 = __shfl_sync(0xffffffffu, pk[ks][0], srcA);
                    uint32_t u1 = __shfl_sync(0xffffffffu, pk[ks][1], srcA);
                    uint32_t u2 = __shfl_sync(0xffffffffu, pk[ks][2], srcA);
                    uint32_t u3 = __shfl_sync(0xffffffffu, pk[ks][3], srcA);
                    uint32_t v0 = __shfl_sync(0xffffffffu, pk[ks][0], srcB);
                    uint32_t v1 = __shfl_sync(0xffffffffu, pk[ks][1], srcB);
                    uint32_t v2 = __shfl_sync(0xffffffffu, pk[ks][2], srcB);
                    uint32_t v3 = __shfl_sync(0xffffffffu, pk[ks][3], srcB);
                    af[0] = (lr & 1) ? u1 : u0;
                    af[1] = (lr & 1) ? u3 : u2;
                    af[2] = (lr & 1) ? v1 : v0;
                    af[3] = (lr & 1) ? v3 : v2;
                }
                int kk = ks * 8;
                #pragma unroll
                for (int nf = 0; nf < 16; nf++) {
                    uint32_t bf[2];
                    int ncol = nf * 8 + lq;
                    bf[0] = f2tf32(Vb[(kk + lr) * V_STRIDE + ncol]);
                    bf[1] = f2tf32(Vb[(kk + lr + 4) * V_STRIDE + ncol]);
                    mma_tf32(oacc[nf], af, bf);
                }
            }
        }

        __syncthreads();

        if (t + 2 < nkv) {
            float* Kd = Kraw + (t & 1) * (64 * K_STRIDE);
            float* Vd = Vraw + (t & 1) * (64 * V_STRIDE);
            const float* kb = qkv + kv_row0 + (size_t)((t + 2) * 64) * QKV3;
            #pragma unroll
            for (int j = 0; j < 8; j++) {
                int i = tid + j * 256;
                int r = i >> 5, dg = (i & 31) << 2;
                cp_async16(Kd + r * K_STRIDE + dg, kb + (size_t)r * QKV3 + dg);
                cp_async16(Vd + r * V_STRIDE + dg, kb + (size_t)r * QKV3 + DIM + dg);
            }
        }
        cp_commit();
    }

    // epilogue -> fp16 (feeds out_proj fp16 GEMM)
    float inv0 = 1.f / l0, inv1 = 1.f / l1;
    int t0 = seq_start + q0 + warp * 16 + lq;
    __half* ob = out + (size_t)t0 * DIM + (size_t)h * HD;
    #pragma unroll
    for (int nf = 0; nf < 16; nf++) {
        int c = nf * 8 + lr * 2;
        *reinterpret_cast<__half2*>(ob + c) =
            __floats2half2_rn(oacc[nf][0] * inv0, oacc[nf][1] * inv0);
        *reinterpret_cast<__half2*>(ob + (size_t)8 * DIM + c) =
            __floats2half2_rn(oacc[nf][2] * inv1, oacc[nf][3] * inv1);
    }
}

// ---------------- sigmoid gate: g = fp16(sigmoid(g) * u) ----------------
__global__ __launch_bounds__(256) void gate_kernel(__half2* __restrict__ g,
                                                   const __half2* __restrict__ u, int n2)
{
    int i = blockIdx.x * blockDim.x + threadIdx.x;
    if (i < n2) {
        float2 gv = __half22float2(g[i]);
        float2 uv = __half22float2(u[i]);
        gv.x = uv.x / (1.f + __expf(-gv.x));
        gv.y = uv.y / (1.f + __expf(-gv.y));
        g[i] = __floats2half2_rn(gv.x, gv.y);
    }
}

// ---------------- launch ----------------
extern "C" void kernel_launch(void* const* d_in, const int* in_sizes, int n_in,
                              void* d_out, int out_size)
{
    const float* hidden     = (const float*)d_in[0];
    const float* ln1_w      = (const float*)d_in[1];
    const float* ln2_w      = (const float*)d_in[2];
    const float* in_proj_w  = (const float*)d_in[3];
    const float* in_proj_b  = (const float*)d_in[4];
    const float* out_proj_w = (const float*)d_in[5];
    const float* out_proj_b = (const float*)d_in[6];
    const float* gate_w     = (const float*)d_in[7];
    const float* up_w       = (const float*)d_in[8];
    const float* down_w     = (const float*)d_in[9];
    float* out = (float*)d_out;

    __half *p_ln, *p_attn, *p_gate, *p_up;
    float  *p_qkv, *p_h2;
    __half *p_wqkv, *p_wout, *p_wgate, *p_wup, *p_wdown;
    cudaGetSymbolAddress((void**)&p_ln,    g_ln);
    cudaGetSymbolAddress((void**)&p_qkv,   g_qkv);
    cudaGetSymbolAddress((void**)&p_attn,  g_attn);
    cudaGetSymbolAddress((void**)&p_h2,    g_h2);
    cudaGetSymbolAddress((void**)&p_gate,  g_gate);
    cudaGetSymbolAddress((void**)&p_up,    g_up);
    cudaGetSymbolAddress((void**)&p_wqkv,  g_wqkv);
    cudaGetSymbolAddress((void**)&p_wout,  g_wout);
    cudaGetSymbolAddress((void**)&p_wgate, g_wgate);
    cudaGetSymbolAddress((void**)&p_wup,   g_wup);
    cudaGetSymbolAddress((void**)&p_wdown, g_wdown);

    cudaFuncSetAttribute((const void*)gemm_f16_kernel,
                         cudaFuncAttributeMaxDynamicSharedMemorySize, GEMM_SMEM_BYTES);
    cudaFuncSetAttribute((const void*)attn_kernel,
                         cudaFuncAttributeMaxDynamicSharedMemorySize, ATTN_SMEM_BYTES);

    int n4;
    // launch 0: qkv weight conversion
    n4 = (QKV3 * DIM) / 4;
    cvtw_kernel<<<(n4 + 255) / 256, 256>>>((const float4*)in_proj_w, (__half2*)p_wqkv, n4);
    // launch 1: rmsnorm1 (fp16 out)
    rmsnorm_kernel<<<TOTAL, 256>>>(hidden, ln1_w, p_ln);
    // launch 2: out-proj weight conversion
    n4 = (DIM * DIM) / 4;
    cvtw_kernel<<<(n4 + 255) / 256, 256>>>((const float4*)out_proj_w, (__half2*)p_wout, n4);
    // launch 3: qkv projection (ncu capture slot)
    gemm_f16_kernel<<<dim3(QKV3 / 128, TOTAL / 128), 256, GEMM_SMEM_BYTES>>>(
        p_ln, p_wqkv, in_proj_b, nullptr, p_qkv, nullptr, TOTAL, QKV3, DIM);
    // launch 4: attention (fp16 out)
    attn_kernel<<<dim3(TOTAL / 128, HEADS), 256, ATTN_SMEM_BYTES>>>(p_qkv, p_attn);
    // launch 5: out projection + residual (fp32 out)
    gemm_f16_kernel<<<dim3(DIM / 128, TOTAL / 128), 256, GEMM_SMEM_BYTES>>>(
        p_attn, p_wout, out_proj_b, hidden, p_h2, nullptr, TOTAL, DIM, DIM);
    // launch 6: rmsnorm2 (fp16 out)
    rmsnorm_kernel<<<TOTAL, 256>>>(p_h2, ln2_w, p_ln);
    // launches 7,8: gate & up weight conversions
    n4 = (FDIM * DIM) / 4;
    cvtw_kernel<<<(n4 + 255) / 256, 256>>>((const float4*)gate_w, (__half2*)p_wgate, n4);
    cvtw_kernel<<<(n4 + 255) / 256, 256>>>((const float4*)up_w, (__half2*)p_wup, n4);
    // launches 9,10: gate & up projections (fp16 out)
    gemm_f16_kernel<<<dim3(FDIM / 128, TOTAL / 128), 256, GEMM_SMEM_BYTES>>>(
        p_ln, p_wgate, nullptr, nullptr, nullptr, p_gate, TOTAL, FDIM, DIM);
    gemm_f16_kernel<<<dim3(FDIM / 128, TOTAL / 128), 256, GEMM_SMEM_BYTES>>>(
        p_ln, p_wup, nullptr, nullptr, nullptr, p_up, TOTAL, FDIM, DIM);
    // launch 11: down weight conversion
    cvtw_kernel<<<(n4 + 255) / 256, 256>>>((const float4*)down_w, (__half2*)p_wdown, n4);
    // launch 12: sigmoid gate (fp16 out)
    int n2 = (TOTAL * FDIM) / 2;
    gate_kernel<<<(n2 + 255) / 256, 256>>>((__half2*)p_gate, (const __half2*)p_up, n2);
    // launch 13: down projection + residual -> output (fp32)
    gemm_f16_kernel<<<dim3(DIM / 128, TOTAL / 128), 256, GEMM_SMEM_BYTES>>>(
        p_gate, p_wdown, nullptr, p_h2, out, nullptr, TOTAL, DIM, FDIM);
}

// round 14
// speedup vs baseline: 2.0309x; 1.1199x over previous
#include <cuda_runtime.h>
#include <cuda_fp16.h>
#include <cstdint>

#define TOTAL   9216
#define DIM     2048
#define HEADS   16
#define HD      128
#define FDIM    8192
#define QKV3    6144

// ---------------- scratch (device globals: allocation-free) ----------------
__device__ __half g_ln  [(size_t)TOTAL * DIM];
__device__ __half g_qkv [(size_t)TOTAL * QKV3];
__device__ __half g_attn[(size_t)TOTAL * DIM];
__device__ float  g_h2  [(size_t)TOTAL * DIM];
__device__ __half g_gu  [(size_t)TOTAL * FDIM];     // fused up*sigmoid(gate)
// fp16 weight copies
__device__ __half g_wqkv [(size_t)QKV3 * DIM];
__device__ __half g_wout [(size_t)DIM * DIM];
__device__ __half g_wgu  [(size_t)2 * FDIM * DIM];  // interleaved gate/up rows
__device__ __half g_wdown[(size_t)DIM * FDIM];

__device__ const int c_seqlen[8] = {512, 1024, 2048, 768, 1536, 896, 1280, 1152};

// ---------------- helpers ----------------
__device__ __forceinline__ void mma_f16(float* c, const uint32_t* a, const uint32_t* b) {
    asm("mma.sync.aligned.m16n8k16.row.col.f32.f16.f16.f32 "
        "{%0,%1,%2,%3},{%4,%5,%6,%7},{%8,%9},{%0,%1,%2,%3};"
        : "+f"(c[0]), "+f"(c[1]), "+f"(c[2]), "+f"(c[3])
        : "r"(a[0]), "r"(a[1]), "r"(a[2]), "r"(a[3]), "r"(b[0]), "r"(b[1]));
}

__device__ __forceinline__ void ldsm_x4(uint32_t* r, uint32_t addr) {
    asm volatile("ldmatrix.sync.aligned.m8n8.x4.shared.b16 {%0,%1,%2,%3}, [%4];"
        : "=r"(r[0]), "=r"(r[1]), "=r"(r[2]), "=r"(r[3]) : "r"(addr));
}
__device__ __forceinline__ void ldsm_x4_t(uint32_t* r, uint32_t addr) {
    asm volatile("ldmatrix.sync.aligned.m8n8.x4.trans.shared.b16 {%0,%1,%2,%3}, [%4];"
        : "=r"(r[0]), "=r"(r[1]), "=r"(r[2]), "=r"(r[3]) : "r"(addr));
}

__device__ __forceinline__ void cp_async16(void* smem_dst, const void* gmem_src) {
    uint32_t s = (uint32_t)__cvta_generic_to_shared(smem_dst);
    asm volatile("cp.async.cg.shared.global [%0], [%1], 16;" :: "r"(s), "l"(gmem_src));
}
__device__ __forceinline__ void cp_commit() {
    asm volatile("cp.async.commit_group;");
}

// mbarrier primitives
__device__ __forceinline__ void mbar_init(uint32_t addr, uint32_t count) {
    asm volatile("mbarrier.init.shared.b64 [%0], %1;" :: "r"(addr), "r"(count) : "memory");
}
__device__ __forceinline__ void mbar_arrive(uint32_t addr) {
    asm volatile("mbarrier.arrive.shared.b64 _, [%0];" :: "r"(addr) : "memory");
}
__device__ __forceinline__ void cp_mbar_arrive(uint32_t addr) {
    asm volatile("cp.async.mbarrier.arrive.noinc.shared.b64 [%0];" :: "r"(addr) : "memory");
}
__device__ __forceinline__ void mbar_wait(uint32_t addr, uint32_t parity) {
    asm volatile(
        "{\n\t.reg .pred P;\n\t"
        "W%=:\n\t"
        "mbarrier.try_wait.parity.shared.b64 P, [%0], %1;\n\t"
        "@!P bra W%=;\n\t}"
        :: "r"(addr), "r"(parity) : "memory");
}

// ================= fp16 GEMM, barrier-free mbarrier pipeline =================
// 128x128 tile, 256 threads, K-chunk 64, 3-stage cp.async + per-stage mbarriers.
#define HSTRIDE 72
#define A_HALFS (128 * HSTRIDE)
#define STAGE_HALFS (2 * A_HALFS)
#define STAGE_BYTES (STAGE_HALFS * 2)
#define GEMM_SMEM_BYTES (3 * STAGE_BYTES + 64)

__device__ __forceinline__ void h_load_stage(const __half* __restrict__ Ab,
                                             const __half* __restrict__ Bb,
                                             int K, __half* As, __half* Bs, int tid)
{
    #pragma unroll
    for (int j = 0; j < 4; j++) {
        int id = tid + j * 256;
        int r = id >> 3, g = (id & 7) << 3;
        cp_async16(As + r * HSTRIDE + g, Ab + (size_t)r * K + g);
        cp_async16(Bs + r * HSTRIDE + g, Bb + (size_t)r * K + g);
    }
}

// Output modes: Cg (gated fp16, N/2 cols) > Ch (fp16) > Cf (fp32)
__global__ __launch_bounds__(256, 2) void gemm_f16_kernel(
    const __half* __restrict__ A, const __half* __restrict__ B,
    const float* __restrict__ bias, const float* __restrict__ resid,
    float* __restrict__ Cf, __half* __restrict__ Ch, __half* __restrict__ Cg,
    int M, int N, int K)
{
    extern __shared__ __half hsm[];
    const uint32_t smemBase = (uint32_t)__cvta_generic_to_shared(hsm);

    const int tid  = threadIdx.x;
    const int lane = tid & 31, warp = tid >> 5;
    const int lq = lane >> 2, lr = lane & 3;
    const int wm = (warp >> 2) * 64, wn = (warp & 3) * 32;
    const int bm = blockIdx.y * 128, bn = blockIdx.x * 128;

    const int tr = lane & 7, th = (lane >> 3) & 1, tq = lane >> 4;
    const uint32_t aoff = (uint32_t)(((wm + tr + th * 8) * HSTRIDE + tq * 8) * 2);
    const uint32_t boff = (uint32_t)(((wn + tr + th * 8) * HSTRIDE + tq * 8) * 2);

    const uint32_t barB = smemBase + 3 * STAGE_BYTES;

    float acc[4][4][4];
    #pragma unroll
    for (int mf = 0; mf < 4; mf++)
        #pragma unroll
        for (int nf = 0; nf < 4; nf++)
            #pragma unroll
            for (int e = 0; e < 4; e++) acc[mf][nf][e] = 0.f;

    const __half* Abase = A + (size_t)bm * K;
    const __half* Bbase = B + (size_t)bn * K;
    const int nk = K >> 6;

    if (tid < 3) {
        mbar_init(barB + 8 * tid, 256);        // full[s]
        mbar_init(barB + 24 + 8 * tid, 256);   // empty[s]
    }
    __syncthreads();

    #pragma unroll
    for (int s = 0; s < 2; s++) {
        __half* As = hsm + s * STAGE_HALFS;
        __half* Bs = As + A_HALFS;
        h_load_stage(Abase + s * 64, Bbase + s * 64, K, As, Bs, tid);
        cp_mbar_arrive(barB + 8 * s);
    }

    for (int i = 0; i < nk; i++) {
        const int st = i % 3;
        mbar_wait(barB + 8 * st, (uint32_t)((i / 3) & 1));

        const uint32_t stOff = smemBase + (uint32_t)(st * STAGE_BYTES);
        const uint32_t aBase = stOff + aoff;
        const uint32_t bBase = stOff + (uint32_t)(A_HALFS * 2) + boff;

        #pragma unroll
        for (int ks = 0; ks < 4; ks++) {
            const uint32_t kOff = (uint32_t)(ks * 32);
            uint32_t af[4][4];
            #pragma unroll
            for (int mf = 0; mf < 4; mf++)
                ldsm_x4(af[mf], aBase + (uint32_t)(mf * 16 * HSTRIDE * 2) + kOff);
            uint32_t b0[4], b1[4];
            ldsm_x4(b0, bBase + kOff);
            ldsm_x4(b1, bBase + (uint32_t)(16 * HSTRIDE * 2) + kOff);
            uint32_t bf[4][2] = {{b0[0], b0[2]}, {b0[1], b0[3]},
                                 {b1[0], b1[2]}, {b1[1], b1[3]}};
            #pragma unroll
            for (int mf = 0; mf < 4; mf++)
                #pragma unroll
                for (int nf = 0; nf < 4; nf++)
                    mma_f16(acc[mf][nf], af[mf], bf[nf]);
        }
        mbar_arrive(barB + 24 + 8 * st);

        const int c = i + 2;
        if (c < nk) {
            const int ps = c % 3;
            if (c >= 3)
                mbar_wait(barB + 24 + 8 * ps, (uint32_t)(((c / 3) - 1) & 1));
            __half* Ad = hsm + ps * STAGE_HALFS;
            __half* Bd = Ad + A_HALFS;
            h_load_stage(Abase + (size_t)c * 64, Bbase + (size_t)c * 64, K, Ad, Bd, tid);
            cp_mbar_arrive(barB + 8 * ps);
        }
    }

    // epilogue
    #pragma unroll
    for (int mf = 0; mf < 4; mf++) {
        #pragma unroll
        for (int nf = 0; nf < 4; nf++) {
            int r0 = bm + wm + mf * 16 + lq;
            int c0 = bn + wn + nf * 8 + lr * 2;
            float b0 = 0.f, b1 = 0.f;
            if (bias) { b0 = bias[c0]; b1 = bias[c0 + 1]; }
            float2 v0 = make_float2(acc[mf][nf][0] + b0, acc[mf][nf][1] + b1);
            float2 v1 = make_float2(acc[mf][nf][2] + b0, acc[mf][nf][3] + b1);
            if (resid) {
                float2 ra = *reinterpret_cast<const float2*>(resid + (size_t)r0 * N + c0);
                float2 rb = *reinterpret_cast<const float2*>(resid + (size_t)(r0 + 8) * N + c0);
                v0.x += ra.x; v0.y += ra.y;
                v1.x += rb.x; v1.y += rb.y;
            }
            if (Cg) {
                // interleaved gate/up: even col = gate, odd col = up
                int f = c0 >> 1;
                float h0 = v0.y / (1.f + __expf(-v0.x));
                float h1 = v1.y / (1.f + __expf(-v1.x));
                Cg[(size_t)r0 * (N >> 1) + f]       = __float2half_rn(h0);
                Cg[(size_t)(r0 + 8) * (N >> 1) + f] = __float2half_rn(h1);
            } else if (Ch) {
                *reinterpret_cast<__half2*>(Ch + (size_t)r0 * N + c0) =
                    __floats2half2_rn(v0.x, v0.y);
                *reinterpret_cast<__half2*>(Ch + (size_t)(r0 + 8) * N + c0) =
                    __floats2half2_rn(v1.x, v1.y);
            } else {
                *reinterpret_cast<float2*>(Cf + (size_t)r0 * N + c0) = v0;
                *reinterpret_cast<float2*>(Cf + (size_t)(r0 + 8) * N + c0) = v1;
            }
        }
    }
}

// ---------------- weight converts ----------------
__global__ __launch_bounds__(256) void cvtw_kernel(const float4* __restrict__ in,
                                                   __half2* __restrict__ out, int n4)
{
    int i = blockIdx.x * blockDim.x + threadIdx.x;
    if (i < n4) {
        float4 v = in[i];
        out[2 * i]     = __floats2half2_rn(v.x, v.y);
        out[2 * i + 1] = __floats2half2_rn(v.z, v.w);
    }
}

// interleave gate/up rows: out row 2f = gate f, row 2f+1 = up f
__global__ __launch_bounds__(256) void cvtw2_kernel(const float4* __restrict__ gw,
                                                    const float4* __restrict__ uw,
                                                    __half2* __restrict__ out, int n4)
{
    int i = blockIdx.x * blockDim.x + threadIdx.x;
    if (i < n4) {
        int f = i >> 9;            // DIM/4 = 512 float4 per row
        int c4 = i & 511;
        float4 g = gw[i];
        float4 u = uw[i];
        size_t og = ((size_t)(2 * f) * 512 + c4) * 2;
        size_t ou = ((size_t)(2 * f + 1) * 512 + c4) * 2;
        out[og]     = __floats2half2_rn(g.x, g.y);
        out[og + 1] = __floats2half2_rn(g.z, g.w);
        out[ou]     = __floats2half2_rn(u.x, u.y);
        out[ou + 1] = __floats2half2_rn(u.z, u.w);
    }
}

// ---------------- RMSNorm (fp32 in, fp16 out) ----------------
__global__ __launch_bounds__(256) void rmsnorm_kernel(const float* __restrict__ x,
                                                      const float* __restrict__ w,
                                                      __half* __restrict__ y)
{
    int row = blockIdx.x;
    const float4* xr = reinterpret_cast<const float4*>(x + (size_t)row * DIM);
    __half2*      yr = reinterpret_cast<__half2*>(y + (size_t)row * DIM);
    const float4* wr = reinterpret_cast<const float4*>(w);
    int tid = threadIdx.x;

    float4 v0 = xr[tid];
    float4 v1 = xr[tid + 256];
    float ss = v0.x*v0.x + v0.y*v0.y + v0.z*v0.z + v0.w*v0.w
             + v1.x*v1.x + v1.y*v1.y + v1.z*v1.z + v1.w*v1.w;
    #pragma unroll
    for (int o = 16; o; o >>= 1) ss += __shfl_xor_sync(0xffffffffu, ss, o);

    __shared__ float red[8];
    __shared__ float stot;
    if ((tid & 31) == 0) red[tid >> 5] = ss;
    __syncthreads();
    if (tid == 0) {
        float t = 0.f;
        #pragma unroll
        for (int i = 0; i < 8; i++) t += red[i];
        stot = rsqrtf(t * (1.0f / (float)DIM) + 1e-6f);
    }
    __syncthreads();
    float r = stot;

    float4 w0 = wr[tid], w1 = wr[tid + 256];
    yr[2 * tid]             = __floats2half2_rn(v0.x*r*w0.x, v0.y*r*w0.y);
    yr[2 * tid + 1]         = __floats2half2_rn(v0.z*r*w0.z, v0.w*r*w0.w);
    yr[2 * (tid + 256)]     = __floats2half2_rn(v1.x*r*w1.x, v1.y*r*w1.y);
    yr[2 * (tid + 256) + 1] = __floats2half2_rn(v1.z*r*w1.z, v1.w*r*w1.w);
}

// ---------------- Flash attention v3: fp16 mma throughout ----------------
// 256 threads (8 warps), 128-row Q tile, 64-row K/V tiles double-buffered.
// Q/K: [rows][128] fp16 stride 136 (272B rows -> conflict-free ldsm).
// V:   [kv][128dim] fp16 stride 136, b-frags via ldmatrix.x4.trans.
// P: fp16 half2 packs straight from S c-frags (no shuffles). 2 CTAs/SM.
#define AQ_STRIDE 136
#define AK_STRIDE 136
#define AV_STRIDE 136
#define LOG2E 1.4426950408889634f

#define AQ_HALFS (128 * AQ_STRIDE)
#define AK_HALFS (64 * AK_STRIDE)
#define AV_HALFS (64 * AV_STRIDE)
#define ATTN_SMEM_BYTES ((AQ_HALFS + 2 * AK_HALFS + 2 * AV_HALFS) * 2)

__global__ __launch_bounds__(256, 2) void attn_kernel(const __half* __restrict__ qkv,
                                                      __half* __restrict__ out)
{
    extern __shared__ __half asmem[];
    __half* Qs = asmem;
    __half* Ks = Qs + AQ_HALFS;
    __half* Vs = Ks + 2 * AK_HALFS;
    const uint32_t smemBase = (uint32_t)__cvta_generic_to_shared(asmem);
    const uint32_t QsB = smemBase;
    const uint32_t KsB = QsB + AQ_HALFS * 2;
    const uint32_t VsB = KsB + 2 * AK_HALFS * 2;

    const int tile = blockIdx.x;
    const int h    = blockIdx.y;

    int seq_start = 0, q0 = 0;
    {
        int acc = 0, start = 0;
        #pragma unroll
        for (int s = 0; s < 8; s++) {
            int nt = c_seqlen[s] >> 7;
            if (tile >= acc && tile < acc + nt) {
                seq_start = start; q0 = (tile - acc) << 7;
            }
            acc += nt; start += c_seqlen[s];
        }
    }

    const int tid = threadIdx.x, lane = tid & 31, warp = tid >> 5;
    const int lq = lane >> 2, lr = lane & 3;
    const int nkv = (q0 >> 6) + 2;

    const size_t q_row0  = (size_t)(seq_start + q0) * QKV3 + (size_t)h * HD;
    const size_t kv_row0 = (size_t)seq_start * QKV3 + DIM + (size_t)h * HD;

    // ldsm lane mapping
    const int tr = lane & 7, th = (lane >> 3) & 1, tq = lane >> 4;
    const uint32_t aoff = (uint32_t)(((warp * 16 + tr + th * 8) * AQ_STRIDE + tq * 8) * 2);
    const uint32_t koff = (uint32_t)(((tr + th * 8) * AK_STRIDE + tq * 8) * 2);
    // V trans addr: row = (lane&15), dim sub-offset = (lane>>4)*8
    const uint32_t voff = (uint32_t)(((lane & 15) * AV_STRIDE + ((lane >> 4) << 3)) * 2);

    // prologue: Q group, then KV tiles 0,1
    {
        #pragma unroll
        for (int j = 0; j < 8; j++) {
            int i = tid + j * 256;
            int r = i >> 4, g = (i & 15) << 3;
            cp_async16(Qs + r * AQ_STRIDE + g, qkv + q_row0 + (size_t)r * QKV3 + g);
        }
        cp_commit();
    }
    #pragma unroll
    for (int t = 0; t < 2; t++) {
        __half* Kd = Ks + (t & 1) * AK_HALFS;
        __half* Vd = Vs + (t & 1) * AV_HALFS;
        const __half* kb = qkv + kv_row0 + (size_t)(t * 64) * QKV3;
        #pragma unroll
        for (int j = 0; j < 4; j++) {
            int i = tid + j * 256;
            int r = i >> 4, g = (i & 15) << 3;
            cp_async16(Kd + r * AK_STRIDE + g, kb + (size_t)r * QKV3 + g);
            cp_async16(Vd + r * AV_STRIDE + g, kb + (size_t)r * QKV3 + DIM + g);
        }
        cp_commit();
    }

    float oacc[16][4];
    #pragma unroll
    for (int nf = 0; nf < 16; nf++)
        #pragma unroll
        for (int e = 0; e < 4; e++) oacc[nf][e] = 0.f;
    float m0 = -1e30f, m1 = -1e30f, l0 = 0.f, l1 = 0.f;
    const float scale = 0.08838834764831845f;   // 1/sqrt(128)

    const int qbase_warp = q0 + warp * 16;

    for (int t = 0; t < nkv; t++) {
        asm volatile("cp.async.wait_group 1;");
        __syncthreads();

        const int j0 = t << 6;
        const uint32_t KbB = KsB + (uint32_t)((t & 1) * AK_HALFS * 2);
        const uint32_t VbB = VsB + (uint32_t)((t & 1) * AV_HALFS * 2);
        const bool skipw = (j0 > qbase_warp + 15);

        if (!skipw) {
            // ---- S = Q K^T : 16 q-rows x 64 keys, fp16 k16 mma ----
            float sacc[8][4];
            #pragma unroll
            for (int nf = 0; nf < 8; nf++)
                #pragma unroll
                for (int e = 0; e < 4; e++) sacc[nf][e] = 0.f;

            #pragma unroll
            for (int ks = 0; ks < 8; ks++) {
                const uint32_t kOff = (uint32_t)(ks * 32);   // 16 halves
                uint32_t af[4];
                ldsm_x4(af, QsB + aoff + kOff);
                #pragma unroll
                for (int nb = 0; nb < 4; nb++) {
                    uint32_t b[4];
                    ldsm_x4(b, KbB + koff + (uint32_t)(nb * 16 * AK_STRIDE * 2) + kOff);
                    uint32_t bf0[2] = {b[0], b[2]};
                    uint32_t bf1[2] = {b[1], b[3]};
                    mma_f16(sacc[2 * nb],     af, bf0);
                    mma_f16(sacc[2 * nb + 1], af, bf1);
                }
            }

            // ---- online softmax (fp32) ----
            const bool diag = (j0 + 63 > qbase_warp);
            const int qr0 = qbase_warp + lq;
            const int qr1 = qr0 + 8;
            float mx0 = -1e30f, mx1 = -1e30f;
            #pragma unroll
            for (int nf = 0; nf < 8; nf++) {
                #pragma unroll
                for (int e = 0; e < 4; e++) {
                    float s = sacc[nf][e] * scale;
                    if (diag) {
                        int kc = j0 + nf * 8 + lr * 2 + (e & 1);
                        int qr = (e < 2) ? qr0 : qr1;
                        if (kc > qr) s = -1e30f;
                    }
                    sacc[nf][e] = s;
                }
                mx0 = fmaxf(mx0, fmaxf(sacc[nf][0], sacc[nf][1]));
                mx1 = fmaxf(mx1, fmaxf(sacc[nf][2], sacc[nf][3]));
            }
            mx0 = fmaxf(mx0, __shfl_xor_sync(0xffffffffu, mx0, 1));
            mx0 = fmaxf(mx0, __shfl_xor_sync(0xffffffffu, mx0, 2));
            mx1 = fmaxf(mx1, __shfl_xor_sync(0xffffffffu, mx1, 1));
            mx1 = fmaxf(mx1, __shfl_xor_sync(0xffffffffu, mx1, 2));

            float mn0 = fmaxf(m0, mx0), mn1 = fmaxf(m1, mx1);
            float c0 = exp2f((m0 - mn0) * LOG2E), c1 = exp2f((m1 - mn1) * LOG2E);
            float s0 = 0.f, s1 = 0.f;
            uint32_t pkl[8], pkh[8];   // P fp16 packs: rows lq / lq+8
            #pragma unroll
            for (int nf = 0; nf < 8; nf++) {
                float p0 = exp2f((sacc[nf][0] - mn0) * LOG2E);
                float p1 = exp2f((sacc[nf][1] - mn0) * LOG2E);
                float p2 = exp2f((sacc[nf][2] - mn1) * LOG2E);
                float p3 = exp2f((sacc[nf][3] - mn1) * LOG2E);
                s0 += p0 + p1; s1 += p2 + p3;
                __half2 hl = __floats2half2_rn(p0, p1);
                __half2 hh = __floats2half2_rn(p2, p3);
                pkl[nf] = *reinterpret_cast<uint32_t*>(&hl);
                pkh[nf] = *reinterpret_cast<uint32_t*>(&hh);
            }
            s0 += __shfl_xor_sync(0xffffffffu, s0, 1);
            s0 += __shfl_xor_sync(0xffffffffu, s0, 2);
            s1 += __shfl_xor_sync(0xffffffffu, s1, 1);
            s1 += __shfl_xor_sync(0xffffffffu, s1, 2);
            l0 = l0 * c0 + s0;
            l1 = l1 * c1 + s1;
            m0 = mn0; m1 = mn1;
            #pragma unroll
            for (int nf = 0; nf < 16; nf++) {
                oacc[nf][0] *= c0; oacc[nf][1] *= c0;
                oacc[nf][2] *= c1; oacc[nf][3] *= c1;
            }

            // ---- O += P V : fp16 k16 mma, V b-frags via ldsm.trans ----
            #pragma unroll
            for (int ks = 0; ks < 4; ks++) {
                uint32_t af[4] = {pkl[2 * ks], pkh[2 * ks], pkl[2 * ks + 1], pkh[2 * ks + 1]};
                const uint32_t rowOff = (uint32_t)(ks * 16 * AV_STRIDE * 2);
                #pragma unroll
                for (int q = 0; q < 8; q++) {
                    uint32_t v[4];
                    ldsm_x4_t(v, VbB + voff + rowOff + (uint32_t)(q * 32));  // 16 dims
                    uint32_t bf0[2] = {v[0], v[1]};
                    uint32_t bf1[2] = {v[2], v[3]};
                    mma_f16(oacc[2 * q],     af, bf0);
                    mma_f16(oacc[2 * q + 1], af, bf1);
                }
            }
        }

        __syncthreads();

        if (t + 2 < nkv) {
            __half* Kd = Ks + (t & 1) * AK_HALFS;
            __half* Vd = Vs + (t & 1) * AV_HALFS;
            const __half* kb = qkv + kv_row0 + (size_t)((t + 2) * 64) * QKV3;
            #pragma unroll
            for (int j = 0; j < 4; j++) {
                int i = tid + j * 256;
                int r = i >> 4, g = (i & 15) << 3;
                cp_async16(Kd + r * AK_STRIDE + g, kb + (size_t)r * QKV3 + g);
                cp_async16(Vd + r * AV_STRIDE + g, kb + (size_t)r * QKV3 + DIM + g);
            }
        }
        cp_commit();
    }

    // epilogue -> fp16 (feeds out_proj fp16 GEMM)
    float inv0 = 1.f / l0, inv1 = 1.f / l1;
    int t0 = seq_start + q0 + warp * 16 + lq;
    __half* ob = out + (size_t)t0 * DIM + (size_t)h * HD;
    #pragma unroll
    for (int nf = 0; nf < 16; nf++) {
        int c = nf * 8 + lr * 2;
        *reinterpret_cast<__half2*>(ob + c) =
            __floats2half2_rn(oacc[nf][0] * inv0, oacc[nf][1] * inv0);
        *reinterpret_cast<__half2*>(ob + (size_t)8 * DIM + c) =
            __floats2half2_rn(oacc[nf][2] * inv1, oacc[nf][3] * inv1);
    }
}

// ---------------- launch ----------------
extern "C" void kernel_launch(void* const* d_in, const int* in_sizes, int n_in,
                              void* d_out, int out_size)
{
    const float* hidden     = (const float*)d_in[0];
    const float* ln1_w      = (const float*)d_in[1];
    const float* ln2_w      = (const float*)d_in[2];
    const float* in_proj_w  = (const float*)d_in[3];
    const float* in_proj_b  = (const float*)d_in[4];
    const float* out_proj_w = (const float*)d_in[5];
    const float* out_proj_b = (const float*)d_in[6];
    const float* gate_w     = (const float*)d_in[7];
    const float* up_w       = (const float*)d_in[8];
    const float* down_w     = (const float*)d_in[9];
    float* out = (float*)d_out;

    __half *p_ln, *p_qkv, *p_attn, *p_gu;
    float  *p_h2;
    __half *p_wqkv, *p_wout, *p_wgu, *p_wdown;
    cudaGetSymbolAddress((void**)&p_ln,    g_ln);
    cudaGetSymbolAddress((void**)&p_qkv,   g_qkv);
    cudaGetSymbolAddress((void**)&p_attn,  g_attn);
    cudaGetSymbolAddress((void**)&p_h2,    g_h2);
    cudaGetSymbolAddress((void**)&p_gu,    g_gu);
    cudaGetSymbolAddress((void**)&p_wqkv,  g_wqkv);
    cudaGetSymbolAddress((void**)&p_wout,  g_wout);
    cudaGetSymbolAddress((void**)&p_wgu,   g_wgu);
    cudaGetSymbolAddress((void**)&p_wdown, g_wdown);

    cudaFuncSetAttribute((const void*)gemm_f16_kernel,
                         cudaFuncAttributeMaxDynamicSharedMemorySize, GEMM_SMEM_BYTES);
    cudaFuncSetAttribute((const void*)attn_kernel,
                         cudaFuncAttributeMaxDynamicSharedMemorySize, ATTN_SMEM_BYTES);

    int n4;
    // launch 0: qkv weight conversion
    n4 = (QKV3 * DIM) / 4;
    cvtw_kernel<<<(n4 + 255) / 256, 256>>>((const float4*)in_proj_w, (__half2*)p_wqkv, n4);
    // launch 1: rmsnorm1 (fp16 out)
    rmsnorm_kernel<<<TOTAL, 256>>>(hidden, ln1_w, p_ln);
    // launch 2: qkv projection (fp16 out)
    gemm_f16_kernel<<<dim3(QKV3 / 128, TOTAL / 128), 256, GEMM_SMEM_BYTES>>>(
        p_ln, p_wqkv, in_proj_b, nullptr, nullptr, p_qkv, nullptr, TOTAL, QKV3, DIM);
    // launch 3: attention (ncu capture slot)
    attn_kernel<<<dim3(TOTAL / 128, HEADS), 256, ATTN_SMEM_BYTES>>>(p_qkv, p_attn);
    // launch 4: out-proj weight conversion
    n4 = (DIM * DIM) / 4;
    cvtw_kernel<<<(n4 + 255) / 256, 256>>>((const float4*)out_proj_w, (__half2*)p_wout, n4);
    // launch 5: out projection + residual (fp32 out)
    gemm_f16_kernel<<<dim3(DIM / 128, TOTAL / 128), 256, GEMM_SMEM_BYTES>>>(
        p_attn, p_wout, out_proj_b, hidden, p_h2, nullptr, nullptr, TOTAL, DIM, DIM);
    // launch 6: rmsnorm2 (fp16 out)
    rmsnorm_kernel<<<TOTAL, 256>>>(p_h2, ln2_w, p_ln);
    // launch 7: gate+up interleaved weight conversion
    n4 = (FDIM * DIM) / 4;
    cvtw2_kernel<<<(n4 + 255) / 256, 256>>>((const float4*)gate_w, (const float4*)up_w,
                                            (__half2*)p_wgu, n4);
    // launch 8: fused gate/up projection + sigmoid-gate epilogue (fp16 out)
    gemm_f16_kernel<<<dim3((2 * FDIM) / 128, TOTAL / 128), 256, GEMM_SMEM_BYTES>>>(
        p_ln, p_wgu, nullptr, nullptr, nullptr, nullptr, p_gu, TOTAL, 2 * FDIM, DIM);
    // launch 9: down weight conversion
    cvtw_kernel<<<(n4 + 255) / 256, 256>>>((const float4*)down_w, (__half2*)p_wdown, n4);
    // launch 10: down projection + residual -> output (fp32)
    gemm_f16_kernel<<<dim3(DIM / 128, TOTAL / 128), 256, GEMM_SMEM_BYTES>>>(
        p_gu, p_wdown, nullptr, p_h2, out, nullptr, nullptr, TOTAL, DIM, FDIM);
}

// round 15
// speedup vs baseline: 2.0313x; 1.0002x over previous
#include <cuda_runtime.h>
#include <cuda_fp16.h>
#include <cstdint>

#define TOTAL   9216
#define DIM     2048
#define HEADS   16
#define HD      128
#define FDIM    8192
#define QKV3    6144

// ---------------- scratch (device globals: allocation-free) ----------------
__device__ __half g_ln  [(size_t)TOTAL * DIM];
__device__ __half g_qkv [(size_t)TOTAL * QKV3];
__device__ __half g_attn[(size_t)TOTAL * DIM];
__device__ float  g_h2  [(size_t)TOTAL * DIM];
__device__ __half g_gu  [(size_t)TOTAL * FDIM];     // fused up*sigmoid(gate)
// fp16 weight copies
__device__ __half g_wqkv [(size_t)QKV3 * DIM];
__device__ __half g_wout [(size_t)DIM * DIM];
__device__ __half g_wgu  [(size_t)2 * FDIM * DIM];  // interleaved gate/up rows
__device__ __half g_wdown[(size_t)DIM * FDIM];

__device__ const int c_seqlen[8] = {512, 1024, 2048, 768, 1536, 896, 1280, 1152};

// ---------------- helpers ----------------
__device__ __forceinline__ void mma_f16(float* c, const uint32_t* a, const uint32_t* b) {
    asm("mma.sync.aligned.m16n8k16.row.col.f32.f16.f16.f32 "
        "{%0,%1,%2,%3},{%4,%5,%6,%7},{%8,%9},{%0,%1,%2,%3};"
        : "+f"(c[0]), "+f"(c[1]), "+f"(c[2]), "+f"(c[3])
        : "r"(a[0]), "r"(a[1]), "r"(a[2]), "r"(a[3]), "r"(b[0]), "r"(b[1]));
}

__device__ __forceinline__ void ldsm_x4(uint32_t* r, uint32_t addr) {
    asm volatile("ldmatrix.sync.aligned.m8n8.x4.shared.b16 {%0,%1,%2,%3}, [%4];"
        : "=r"(r[0]), "=r"(r[1]), "=r"(r[2]), "=r"(r[3]) : "r"(addr));
}
__device__ __forceinline__ void ldsm_x4_t(uint32_t* r, uint32_t addr) {
    asm volatile("ldmatrix.sync.aligned.m8n8.x4.trans.shared.b16 {%0,%1,%2,%3}, [%4];"
        : "=r"(r[0]), "=r"(r[1]), "=r"(r[2]), "=r"(r[3]) : "r"(addr));
}

__device__ __forceinline__ void cp_async16(void* smem_dst, const void* gmem_src) {
    uint32_t s = (uint32_t)__cvta_generic_to_shared(smem_dst);
    asm volatile("cp.async.cg.shared.global [%0], [%1], 16;" :: "r"(s), "l"(gmem_src));
}

// mbarrier primitives
__device__ __forceinline__ void mbar_init(uint32_t addr, uint32_t count) {
    asm volatile("mbarrier.init.shared.b64 [%0], %1;" :: "r"(addr), "r"(count) : "memory");
}
__device__ __forceinline__ void mbar_arrive(uint32_t addr) {
    asm volatile("mbarrier.arrive.shared.b64 _, [%0];" :: "r"(addr) : "memory");
}
__device__ __forceinline__ void cp_mbar_arrive(uint32_t addr) {
    asm volatile("cp.async.mbarrier.arrive.noinc.shared.b64 [%0];" :: "r"(addr) : "memory");
}
__device__ __forceinline__ void mbar_wait(uint32_t addr, uint32_t parity) {
    asm volatile(
        "{\n\t.reg .pred P;\n\t"
        "W%=:\n\t"
        "mbarrier.try_wait.parity.shared.b64 P, [%0], %1;\n\t"
        "@!P bra W%=;\n\t}"
        :: "r"(addr), "r"(parity) : "memory");
}

// ================= fp16 GEMM, barrier-free mbarrier pipeline =================
// 128x128 tile, 256 threads, K-chunk 64, 3-stage cp.async + per-stage mbarriers.
#define HSTRIDE 72
#define A_HALFS (128 * HSTRIDE)
#define STAGE_HALFS (2 * A_HALFS)
#define STAGE_BYTES (STAGE_HALFS * 2)
#define GEMM_SMEM_BYTES (3 * STAGE_BYTES + 64)

__device__ __forceinline__ void h_load_stage(const __half* __restrict__ Ab,
                                             const __half* __restrict__ Bb,
                                             int K, __half* As, __half* Bs, int tid)
{
    #pragma unroll
    for (int j = 0; j < 4; j++) {
        int id = tid + j * 256;
        int r = id >> 3, g = (id & 7) << 3;
        cp_async16(As + r * HSTRIDE + g, Ab + (size_t)r * K + g);
        cp_async16(Bs + r * HSTRIDE + g, Bb + (size_t)r * K + g);
    }
}

// Output modes: Cg (gated fp16, N/2 cols) > Ch (fp16) > Cf (fp32)
__global__ __launch_bounds__(256, 2) void gemm_f16_kernel(
    const __half* __restrict__ A, const __half* __restrict__ B,
    const float* __restrict__ bias, const float* __restrict__ resid,
    float* __restrict__ Cf, __half* __restrict__ Ch, __half* __restrict__ Cg,
    int M, int N, int K)
{
    extern __shared__ __half hsm[];
    const uint32_t smemBase = (uint32_t)__cvta_generic_to_shared(hsm);

    const int tid  = threadIdx.x;
    const int lane = tid & 31, warp = tid >> 5;
    const int lq = lane >> 2, lr = lane & 3;
    const int wm = (warp >> 2) * 64, wn = (warp & 3) * 32;
    const int bm = blockIdx.y * 128, bn = blockIdx.x * 128;

    const int tr = lane & 7, th = (lane >> 3) & 1, tq = lane >> 4;
    const uint32_t aoff = (uint32_t)(((wm + tr + th * 8) * HSTRIDE + tq * 8) * 2);
    const uint32_t boff = (uint32_t)(((wn + tr + th * 8) * HSTRIDE + tq * 8) * 2);

    const uint32_t barB = smemBase + 3 * STAGE_BYTES;

    float acc[4][4][4];
    #pragma unroll
    for (int mf = 0; mf < 4; mf++)
        #pragma unroll
        for (int nf = 0; nf < 4; nf++)
            #pragma unroll
            for (int e = 0; e < 4; e++) acc[mf][nf][e] = 0.f;

    const __half* Abase = A + (size_t)bm * K;
    const __half* Bbase = B + (size_t)bn * K;
    const int nk = K >> 6;

    if (tid < 3) {
        mbar_init(barB + 8 * tid, 256);        // full[s]
        mbar_init(barB + 24 + 8 * tid, 256);   // empty[s]
    }
    __syncthreads();

    #pragma unroll
    for (int s = 0; s < 2; s++) {
        __half* As = hsm + s * STAGE_HALFS;
        __half* Bs = As + A_HALFS;
        h_load_stage(Abase + s * 64, Bbase + s * 64, K, As, Bs, tid);
        cp_mbar_arrive(barB + 8 * s);
    }

    for (int i = 0; i < nk; i++) {
        const int st = i % 3;
        mbar_wait(barB + 8 * st, (uint32_t)((i / 3) & 1));

        const uint32_t stOff = smemBase + (uint32_t)(st * STAGE_BYTES);
        const uint32_t aBase = stOff + aoff;
        const uint32_t bBase = stOff + (uint32_t)(A_HALFS * 2) + boff;

        #pragma unroll
        for (int ks = 0; ks < 4; ks++) {
            const uint32_t kOff = (uint32_t)(ks * 32);
            uint32_t af[4][4];
            #pragma unroll
            for (int mf = 0; mf < 4; mf++)
                ldsm_x4(af[mf], aBase + (uint32_t)(mf * 16 * HSTRIDE * 2) + kOff);
            uint32_t b0[4], b1[4];
            ldsm_x4(b0, bBase + kOff);
            ldsm_x4(b1, bBase + (uint32_t)(16 * HSTRIDE * 2) + kOff);
            uint32_t bf[4][2] = {{b0[0], b0[2]}, {b0[1], b0[3]},
                                 {b1[0], b1[2]}, {b1[1], b1[3]}};
            #pragma unroll
            for (int mf = 0; mf < 4; mf++)
                #pragma unroll
                for (int nf = 0; nf < 4; nf++)
                    mma_f16(acc[mf][nf], af[mf], bf[nf]);
        }
        mbar_arrive(barB + 24 + 8 * st);

        const int c = i + 2;
        if (c < nk) {
            const int ps = c % 3;
            if (c >= 3)
                mbar_wait(barB + 24 + 8 * ps, (uint32_t)(((c / 3) - 1) & 1));
            __half* Ad = hsm + ps * STAGE_HALFS;
            __half* Bd = Ad + A_HALFS;
            h_load_stage(Abase + (size_t)c * 64, Bbase + (size_t)c * 64, K, Ad, Bd, tid);
            cp_mbar_arrive(barB + 8 * ps);
        }
    }

    // epilogue
    #pragma unroll
    for (int mf = 0; mf < 4; mf++) {
        #pragma unroll
        for (int nf = 0; nf < 4; nf++) {
            int r0 = bm + wm + mf * 16 + lq;
            int c0 = bn + wn + nf * 8 + lr * 2;
            float b0 = 0.f, b1 = 0.f;
            if (bias) { b0 = bias[c0]; b1 = bias[c0 + 1]; }
            float2 v0 = make_float2(acc[mf][nf][0] + b0, acc[mf][nf][1] + b1);
            float2 v1 = make_float2(acc[mf][nf][2] + b0, acc[mf][nf][3] + b1);
            if (resid) {
                float2 ra = *reinterpret_cast<const float2*>(resid + (size_t)r0 * N + c0);
                float2 rb = *reinterpret_cast<const float2*>(resid + (size_t)(r0 + 8) * N + c0);
                v0.x += ra.x; v0.y += ra.y;
                v1.x += rb.x; v1.y += rb.y;
            }
            if (Cg) {
                int f = c0 >> 1;
                float h0 = v0.y / (1.f + __expf(-v0.x));
                float h1 = v1.y / (1.f + __expf(-v1.x));
                Cg[(size_t)r0 * (N >> 1) + f]       = __float2half_rn(h0);
                Cg[(size_t)(r0 + 8) * (N >> 1) + f] = __float2half_rn(h1);
            } else if (Ch) {
                *reinterpret_cast<__half2*>(Ch + (size_t)r0 * N + c0) =
                    __floats2half2_rn(v0.x, v0.y);
                *reinterpret_cast<__half2*>(Ch + (size_t)(r0 + 8) * N + c0) =
                    __floats2half2_rn(v1.x, v1.y);
            } else {
                *reinterpret_cast<float2*>(Cf + (size_t)r0 * N + c0) = v0;
                *reinterpret_cast<float2*>(Cf + (size_t)(r0 + 8) * N + c0) = v1;
            }
        }
    }
}

// ---------------- weight converts ----------------
__global__ __launch_bounds__(256) void cvtw_kernel(const float4* __restrict__ in,
                                                   __half2* __restrict__ out, int n4)
{
    int i = blockIdx.x * blockDim.x + threadIdx.x;
    if (i < n4) {
        float4 v = in[i];
        out[2 * i]     = __floats2half2_rn(v.x, v.y);
        out[2 * i + 1] = __floats2half2_rn(v.z, v.w);
    }
}

// interleave gate/up rows: out row 2f = gate f, row 2f+1 = up f
__global__ __launch_bounds__(256) void cvtw2_kernel(const float4* __restrict__ gw,
                                                    const float4* __restrict__ uw,
                                                    __half2* __restrict__ out, int n4)
{
    int i = blockIdx.x * blockDim.x + threadIdx.x;
    if (i < n4) {
        int f = i >> 9;            // DIM/4 = 512 float4 per row
        int c4 = i & 511;
        float4 g = gw[i];
        float4 u = uw[i];
        size_t og = ((size_t)(2 * f) * 512 + c4) * 2;
        size_t ou = ((size_t)(2 * f + 1) * 512 + c4) * 2;
        out[og]     = __floats2half2_rn(g.x, g.y);
        out[og + 1] = __floats2half2_rn(g.z, g.w);
        out[ou]     = __floats2half2_rn(u.x, u.y);
        out[ou + 1] = __floats2half2_rn(u.z, u.w);
    }
}

// ---------------- RMSNorm (fp32 in, fp16 out) ----------------
__global__ __launch_bounds__(256) void rmsnorm_kernel(const float* __restrict__ x,
                                                      const float* __restrict__ w,
                                                      __half* __restrict__ y)
{
    int row = blockIdx.x;
    const float4* xr = reinterpret_cast<const float4*>(x + (size_t)row * DIM);
    __half2*      yr = reinterpret_cast<__half2*>(y + (size_t)row * DIM);
    const float4* wr = reinterpret_cast<const float4*>(w);
    int tid = threadIdx.x;

    float4 v0 = xr[tid];
    float4 v1 = xr[tid + 256];
    float ss = v0.x*v0.x + v0.y*v0.y + v0.z*v0.z + v0.w*v0.w
             + v1.x*v1.x + v1.y*v1.y + v1.z*v1.z + v1.w*v1.w;
    #pragma unroll
    for (int o = 16; o; o >>= 1) ss += __shfl_xor_sync(0xffffffffu, ss, o);

    __shared__ float red[8];
    __shared__ float stot;
    if ((tid & 31) == 0) red[tid >> 5] = ss;
    __syncthreads();
    if (tid == 0) {
        float t = 0.f;
        #pragma unroll
        for (int i = 0; i < 8; i++) t += red[i];
        stot = rsqrtf(t * (1.0f / (float)DIM) + 1e-6f);
    }
    __syncthreads();
    float r = stot;

    float4 w0 = wr[tid], w1 = wr[tid + 256];
    yr[2 * tid]             = __floats2half2_rn(v0.x*r*w0.x, v0.y*r*w0.y);
    yr[2 * tid + 1]         = __floats2half2_rn(v0.z*r*w0.z, v0.w*r*w0.w);
    yr[2 * (tid + 256)]     = __floats2half2_rn(v1.x*r*w1.x, v1.y*r*w1.y);
    yr[2 * (tid + 256) + 1] = __floats2half2_rn(v1.z*r*w1.z, v1.w*r*w1.w);
}

// ---------------- Flash attention v4: fp16 mma + mbarrier free-running pipeline ----------------
// 256 threads (8 warps), 128-row Q tile, 64-row K/V tiles double-buffered.
// No __syncthreads in mainloop: full/empty mbarriers per KV buffer + Q-ready barrier.
// Warps skew up to one KV tile: one warp's softmax overlaps another's mma. 2 CTAs/SM.
#define AQ_STRIDE 136
#define AK_STRIDE 136
#define AV_STRIDE 136
#define LOG2E 1.4426950408889634f

#define AQ_HALFS (128 * AQ_STRIDE)
#define AK_HALFS (64 * AK_STRIDE)
#define AV_HALFS (64 * AV_STRIDE)
#define ATTN_DATA_BYTES ((AQ_HALFS + 2 * AK_HALFS + 2 * AV_HALFS) * 2)
#define ATTN_SMEM_BYTES (ATTN_DATA_BYTES + 64)

__global__ __launch_bounds__(256, 2) void attn_kernel(const __half* __restrict__ qkv,
                                                      __half* __restrict__ out)
{
    extern __shared__ __half asmem[];
    __half* Qs = asmem;
    __half* Ks = Qs + AQ_HALFS;
    __half* Vs = Ks + 2 * AK_HALFS;
    const uint32_t smemBase = (uint32_t)__cvta_generic_to_shared(asmem);
    const uint32_t QsB = smemBase;
    const uint32_t KsB = QsB + AQ_HALFS * 2;
    const uint32_t VsB = KsB + 2 * AK_HALFS * 2;
    // barriers: full[0],full[1] = +0,+8 ; empty[0],empty[1] = +16,+24 ; qbar = +32
    const uint32_t barB = smemBase + ATTN_DATA_BYTES;

    const int tile = blockIdx.x;
    const int h    = blockIdx.y;

    int seq_start = 0, q0 = 0;
    {
        int acc = 0, start = 0;
        #pragma unroll
        for (int s = 0; s < 8; s++) {
            int nt = c_seqlen[s] >> 7;
            if (tile >= acc && tile < acc + nt) {
                seq_start = start; q0 = (tile - acc) << 7;
            }
            acc += nt; start += c_seqlen[s];
        }
    }

    const int tid = threadIdx.x, lane = tid & 31, warp = tid >> 5;
    const int lq = lane >> 2, lr = lane & 3;
    const int nkv = (q0 >> 6) + 2;

    const size_t q_row0  = (size_t)(seq_start + q0) * QKV3 + (size_t)h * HD;
    const size_t kv_row0 = (size_t)seq_start * QKV3 + DIM + (size_t)h * HD;

    // ldsm lane mapping
    const int tr = lane & 7, th = (lane >> 3) & 1, tq = lane >> 4;
    const uint32_t aoff = (uint32_t)(((warp * 16 + tr + th * 8) * AQ_STRIDE + tq * 8) * 2);
    const uint32_t koff = (uint32_t)(((tr + th * 8) * AK_STRIDE + tq * 8) * 2);
    const uint32_t voff = (uint32_t)(((lane & 15) * AV_STRIDE + ((lane >> 4) << 3)) * 2);

    if (tid == 0) {
        mbar_init(barB + 0, 256);   // full[0]
        mbar_init(barB + 8, 256);   // full[1]
        mbar_init(barB + 16, 256);  // empty[0]
        mbar_init(barB + 24, 256);  // empty[1]
        mbar_init(barB + 32, 256);  // qbar
    }
    __syncthreads();

    // prologue: Q, then KV tiles 0,1 (cp arrive fires when this thread's prior cps done)
    {
        #pragma unroll
        for (int j = 0; j < 8; j++) {
            int i = tid + j * 256;
            int r = i >> 4, g = (i & 15) << 3;
            cp_async16(Qs + r * AQ_STRIDE + g, qkv + q_row0 + (size_t)r * QKV3 + g);
        }
        cp_mbar_arrive(barB + 32);
    }
    #pragma unroll
    for (int t = 0; t < 2; t++) {
        __half* Kd = Ks + (t & 1) * AK_HALFS;
        __half* Vd = Vs + (t & 1) * AV_HALFS;
        const __half* kb = qkv + kv_row0 + (size_t)(t * 64) * QKV3;
        #pragma unroll
        for (int j = 0; j < 4; j++) {
            int i = tid + j * 256;
            int r = i >> 4, g = (i & 15) << 3;
            cp_async16(Kd + r * AK_STRIDE + g, kb + (size_t)r * QKV3 + g);
            cp_async16(Vd + r * AV_STRIDE + g, kb + (size_t)r * QKV3 + DIM + g);
        }
        cp_mbar_arrive(barB + 8 * t);
    }

    float oacc[16][4];
    #pragma unroll
    for (int nf = 0; nf < 16; nf++)
        #pragma unroll
        for (int e = 0; e < 4; e++) oacc[nf][e] = 0.f;
    float m0 = -1e30f, m1 = -1e30f, l0 = 0.f, l1 = 0.f;
    const float scale = 0.08838834764831845f;   // 1/sqrt(128)

    const int qbase_warp = q0 + warp * 16;

    mbar_wait(barB + 32, 0);   // Q tile ready

    for (int t = 0; t < nkv; t++) {
        const int b = t & 1;
        mbar_wait(barB + 8 * b, (uint32_t)((t >> 1) & 1));   // full[b]

        const int j0 = t << 6;
        const uint32_t KbB = KsB + (uint32_t)(b * AK_HALFS * 2);
        const uint32_t VbB = VsB + (uint32_t)(b * AV_HALFS * 2);
        const bool skipw = (j0 > qbase_warp + 15);

        if (!skipw) {
            // ---- S = Q K^T : 16 q-rows x 64 keys, fp16 k16 mma ----
            float sacc[8][4];
            #pragma unroll
            for (int nf = 0; nf < 8; nf++)
                #pragma unroll
                for (int e = 0; e < 4; e++) sacc[nf][e] = 0.f;

            #pragma unroll
            for (int ks = 0; ks < 8; ks++) {
                const uint32_t kOff = (uint32_t)(ks * 32);   // 16 halves
                uint32_t af[4];
                ldsm_x4(af, QsB + aoff + kOff);
                #pragma unroll
                for (int nb = 0; nb < 4; nb++) {
                    uint32_t bq[4];
                    ldsm_x4(bq, KbB + koff + (uint32_t)(nb * 16 * AK_STRIDE * 2) + kOff);
                    uint32_t bf0[2] = {bq[0], bq[2]};
                    uint32_t bf1[2] = {bq[1], bq[3]};
                    mma_f16(sacc[2 * nb],     af, bf0);
                    mma_f16(sacc[2 * nb + 1], af, bf1);
                }
            }

            // ---- online softmax (fp32) ----
            const bool diag = (j0 + 63 > qbase_warp);
            const int qr0 = qbase_warp + lq;
            const int qr1 = qr0 + 8;
            float mx0 = -1e30f, mx1 = -1e30f;
            #pragma unroll
            for (int nf = 0; nf < 8; nf++) {
                #pragma unroll
                for (int e = 0; e < 4; e++) {
                    float s = sacc[nf][e] * scale;
                    if (diag) {
                        int kc = j0 + nf * 8 + lr * 2 + (e & 1);
                        int qr = (e < 2) ? qr0 : qr1;
                        if (kc > qr) s = -1e30f;
                    }
                    sacc[nf][e] = s;
                }
                mx0 = fmaxf(mx0, fmaxf(sacc[nf][0], sacc[nf][1]));
                mx1 = fmaxf(mx1, fmaxf(sacc[nf][2], sacc[nf][3]));
            }
            mx0 = fmaxf(mx0, __shfl_xor_sync(0xffffffffu, mx0, 1));
            mx0 = fmaxf(mx0, __shfl_xor_sync(0xffffffffu, mx0, 2));
            mx1 = fmaxf(mx1, __shfl_xor_sync(0xffffffffu, mx1, 1));
            mx1 = fmaxf(mx1, __shfl_xor_sync(0xffffffffu, mx1, 2));

            float mn0 = fmaxf(m0, mx0), mn1 = fmaxf(m1, mx1);
            float c0 = exp2f((m0 - mn0) * LOG2E), c1 = exp2f((m1 - mn1) * LOG2E);
            float s0 = 0.f, s1 = 0.f;
            uint32_t pkl[8], pkh[8];
            #pragma unroll
            for (int nf = 0; nf < 8; nf++) {
                float p0 = exp2f((sacc[nf][0] - mn0) * LOG2E);
                float p1 = exp2f((sacc[nf][1] - mn0) * LOG2E);
                float p2 = exp2f((sacc[nf][2] - mn1) * LOG2E);
                float p3 = exp2f((sacc[nf][3] - mn1) * LOG2E);
                s0 += p0 + p1; s1 += p2 + p3;
                __half2 hl = __floats2half2_rn(p0, p1);
                __half2 hh = __floats2half2_rn(p2, p3);
                pkl[nf] = *reinterpret_cast<uint32_t*>(&hl);
                pkh[nf] = *reinterpret_cast<uint32_t*>(&hh);
            }
            s0 += __shfl_xor_sync(0xffffffffu, s0, 1);
            s0 += __shfl_xor_sync(0xffffffffu, s0, 2);
            s1 += __shfl_xor_sync(0xffffffffu, s1, 1);
            s1 += __shfl_xor_sync(0xffffffffu, s1, 2);
            l0 = l0 * c0 + s0;
            l1 = l1 * c1 + s1;
            m0 = mn0; m1 = mn1;
            #pragma unroll
            for (int nf = 0; nf < 16; nf++) {
                oacc[nf][0] *= c0; oacc[nf][1] *= c0;
                oacc[nf][2] *= c1; oacc[nf][3] *= c1;
            }

            // ---- O += P V : fp16 k16 mma, V b-frags via ldsm.trans ----
            #pragma unroll
            for (int ks = 0; ks < 4; ks++) {
                uint32_t af[4] = {pkl[2 * ks], pkh[2 * ks], pkl[2 * ks + 1], pkh[2 * ks + 1]};
                const uint32_t rowOff = (uint32_t)(ks * 16 * AV_STRIDE * 2);
                #pragma unroll
                for (int q = 0; q < 8; q++) {
                    uint32_t v[4];
                    ldsm_x4_t(v, VbB + voff + rowOff + (uint32_t)(q * 32));
                    uint32_t bf0[2] = {v[0], v[1]};
                    uint32_t bf1[2] = {v[2], v[3]};
                    mma_f16(oacc[2 * q],     af, bf0);
                    mma_f16(oacc[2 * q + 1], af, bf1);
                }
            }
        }

        mbar_arrive(barB + 16 + 8 * b);   // empty[b]: this thread done with tile t

        // produce tile t+2 into buffer b (freed once ALL threads consumed tile t)
        const int c = t + 2;
        if (c < nkv) {
            mbar_wait(barB + 16 + 8 * b, (uint32_t)(((c >> 1) - 1) & 1));
            __half* Kd = Ks + b * AK_HALFS;
            __half* Vd = Vs + b * AV_HALFS;
            const __half* kb = qkv + kv_row0 + (size_t)(c * 64) * QKV3;
            #pragma unroll
            for (int j = 0; j < 4; j++) {
                int i = tid + j * 256;
                int r = i >> 4, g = (i & 15) << 3;
                cp_async16(Kd + r * AK_STRIDE + g, kb + (size_t)r * QKV3 + g);
                cp_async16(Vd + r * AV_STRIDE + g, kb + (size_t)r * QKV3 + DIM + g);
            }
            cp_mbar_arrive(barB + 8 * b);
        }
    }

    // epilogue -> fp16 (feeds out_proj fp16 GEMM)
    float inv0 = 1.f / l0, inv1 = 1.f / l1;
    int t0 = seq_start + q0 + warp * 16 + lq;
    __half* ob = out + (size_t)t0 * DIM + (size_t)h * HD;
    #pragma unroll
    for (int nf = 0; nf < 16; nf++) {
        int c = nf * 8 + lr * 2;
        *reinterpret_cast<__half2*>(ob + c) =
            __floats2half2_rn(oacc[nf][0] * inv0, oacc[nf][1] * inv0);
        *reinterpret_cast<__half2*>(ob + (size_t)8 * DIM + c) =
            __floats2half2_rn(oacc[nf][2] * inv1, oacc[nf][3] * inv1);
    }
}

// ---------------- launch ----------------
extern "C" void kernel_launch(void* const* d_in, const int* in_sizes, int n_in,
                              void* d_out, int out_size)
{
    const float* hidden     = (const float*)d_in[0];
    const float* ln1_w      = (const float*)d_in[1];
    const float* ln2_w      = (const float*)d_in[2];
    const float* in_proj_w  = (const float*)d_in[3];
    const float* in_proj_b  = (const float*)d_in[4];
    const float* out_proj_w = (const float*)d_in[5];
    const float* out_proj_b = (const float*)d_in[6];
    const float* gate_w     = (const float*)d_in[7];
    const float* up_w       = (const float*)d_in[8];
    const float* down_w     = (const float*)d_in[9];
    float* out = (float*)d_out;

    __half *p_ln, *p_qkv, *p_attn, *p_gu;
    float  *p_h2;
    __half *p_wqkv, *p_wout, *p_wgu, *p_wdown;
    cudaGetSymbolAddress((void**)&p_ln,    g_ln);
    cudaGetSymbolAddress((void**)&p_qkv,   g_qkv);
    cudaGetSymbolAddress((void**)&p_attn,  g_attn);
    cudaGetSymbolAddress((void**)&p_h2,    g_h2);
    cudaGetSymbolAddress((void**)&p_gu,    g_gu);
    cudaGetSymbolAddress((void**)&p_wqkv,  g_wqkv);
    cudaGetSymbolAddress((void**)&p_wout,  g_wout);
    cudaGetSymbolAddress((void**)&p_wgu,   g_wgu);
    cudaGetSymbolAddress((void**)&p_wdown, g_wdown);

    cudaFuncSetAttribute((const void*)gemm_f16_kernel,
                         cudaFuncAttributeMaxDynamicSharedMemorySize, GEMM_SMEM_BYTES);
    cudaFuncSetAttribute((const void*)attn_kernel,
                         cudaFuncAttributeMaxDynamicSharedMemorySize, ATTN_SMEM_BYTES);

    int n4;
    // launch 0: qkv weight conversion
    n4 = (QKV3 * DIM) / 4;
    cvtw_kernel<<<(n4 + 255) / 256, 256>>>((const float4*)in_proj_w, (__half2*)p_wqkv, n4);
    // launch 1: rmsnorm1 (fp16 out)
    rmsnorm_kernel<<<TOTAL, 256>>>(hidden, ln1_w, p_ln);
    // launch 2: qkv projection (fp16 out)
    gemm_f16_kernel<<<dim3(QKV3 / 128, TOTAL / 128), 256, GEMM_SMEM_BYTES>>>(
        p_ln, p_wqkv, in_proj_b, nullptr, nullptr, p_qkv, nullptr, TOTAL, QKV3, DIM);
    // launch 3: attention (ncu capture slot)
    attn_kernel<<<dim3(TOTAL / 128, HEADS), 256, ATTN_SMEM_BYTES>>>(p_qkv, p_attn);
    // launch 4: out-proj weight conversion
    n4 = (DIM * DIM) / 4;
    cvtw_kernel<<<(n4 + 255) / 256, 256>>>((const float4*)out_proj_w, (__half2*)p_wout, n4);
    // launch 5: out projection + residual (fp32 out)
    gemm_f16_kernel<<<dim3(DIM / 128, TOTAL / 128), 256, GEMM_SMEM_BYTES>>>(
        p_attn, p_wout, out_proj_b, hidden, p_h2, nullptr, nullptr, TOTAL, DIM, DIM);
    // launch 6: rmsnorm2 (fp16 out)
    rmsnorm_kernel<<<TOTAL, 256>>>(p_h2, ln2_w, p_ln);
    // launch 7: gate+up interleaved weight conversion
    n4 = (FDIM * DIM) / 4;
    cvtw2_kernel<<<(n4 + 255) / 256, 256>>>((const float4*)gate_w, (const float4*)up_w,
                                            (__half2*)p_wgu, n4);
    // launch 8: fused gate/up projection + sigmoid-gate epilogue (fp16 out)
    gemm_f16_kernel<<<dim3((2 * FDIM) / 128, TOTAL / 128), 256, GEMM_SMEM_BYTES>>>(
        p_ln, p_wgu, nullptr, nullptr, nullptr, nullptr, p_gu, TOTAL, 2 * FDIM, DIM);
    // launch 9: down weight conversion
    cvtw_kernel<<<(n4 + 255) / 256, 256>>>((const float4*)down_w, (__half2*)p_wdown, n4);
    // launch 10: down projection + residual -> output (fp32)
    gemm_f16_kernel<<<dim3(DIM / 128, TOTAL / 128), 256, GEMM_SMEM_BYTES>>>(
        p_gu, p_wdown, nullptr, p_h2, out, nullptr, nullptr, TOTAL, DIM, FDIM);
}